// round 8
// baseline (speedup 1.0000x reference)
#include <cuda_runtime.h>
#include <cuda_bf16.h>
#include <cstdint>

#define CAP    65536
#define HID    512
#define NH     8
#define BATCH  2048
#define TOPK   32
#define NCODE  256
#define CHUNK  256

// ---------------- scratch (static device globals; no allocation) ----------------
__device__ float         g_W[NH * HID];
__device__ unsigned char g_qcode[BATCH];
__device__ unsigned char g_kcode[CAP];
__device__ int           g_top[NCODE * TOPK];   // first-32 key indices per code
__device__ int           g_bcnt[NCODE];
__device__ int           g_qbstart[NCODE];
__device__ int           g_qbcnt[NCODE];
__device__ int           g_qsorted[BATCH];
__device__ float         g_memout[BATCH * HID];

// ---------------- K1: W[n][h] = sum_d hp[n][h][d] ----------------
__global__ void k_reduce_w(const float* __restrict__ hp) {
    int i = blockIdx.x * blockDim.x + threadIdx.x;
    if (i < NH * HID) {
        float s = 0.f;
#pragma unroll
        for (int d = 0; d < 16; d++) s += hp[i * 16 + d];
        g_W[i] = s;
    }
}

// ---------------- K2: LSH code, R rows per warp (fp32 exact) ----------------
template <int R>
__global__ void k_hash(const float* __restrict__ X, unsigned char* __restrict__ out) {
    __shared__ float4 sW4[NH * 128];
    int tid = threadIdx.x;
    for (int i = tid; i < NH * 128; i += 256) sW4[i] = ((const float4*)g_W)[i];
    __syncthreads();
    int warp = tid >> 5, lane = tid & 31;
    int r0 = (blockIdx.x * 8 + warp) * R;
    float acc[R][NH];
#pragma unroll
    for (int r = 0; r < R; r++)
#pragma unroll
        for (int n = 0; n < NH; n++) acc[r][n] = 0.f;

#pragma unroll
    for (int i = 0; i < 4; i++) {
        int j = lane + 32 * i;
        float4 xv[R];
#pragma unroll
        for (int r = 0; r < R; r++)
            xv[r] = ((const float4*)(X + (size_t)(r0 + r) * HID))[j];
#pragma unroll
        for (int n = 0; n < NH; n++) {
            float4 wv = sW4[n * 128 + j];
#pragma unroll
            for (int r = 0; r < R; r++)
                acc[r][n] += xv[r].x * wv.x + xv[r].y * wv.y + xv[r].z * wv.z + xv[r].w * wv.w;
        }
    }
#pragma unroll
    for (int r = 0; r < R; r++)
#pragma unroll
        for (int n = 0; n < NH; n++) {
#pragma unroll
            for (int off = 16; off > 0; off >>= 1)
                acc[r][n] += __shfl_xor_sync(0xffffffffu, acc[r][n], off);
        }
    if (lane == 0) {
#pragma unroll
        for (int r = 0; r < R; r++) {
            unsigned c = 0;
#pragma unroll
            for (int n = 0; n < NH; n++)
                if (acc[r][n] > 0.f) c |= (1u << n);
            out[r0 + r] = (unsigned char)c;
        }
    }
}

// ---------------- K3: barrier-free selection ----------------
// blocks 0..255: direct sweep -> first-32 ascending key indices + count per code
// block 256:     group the 2048 queries (order within bucket irrelevant)
__global__ void __launch_bounds__(256) k_select(void) {
    int b = blockIdx.x, tid = threadIdx.x;
    if (b < NCODE) {
        int w = tid >> 5, lane = tid & 31;
        __shared__ int warpcnt[8];
        int total = 0;
        for (int it = 0; it < CAP / 1024; it++) {
            uchar4 c = ((const uchar4*)g_kcode)[it * 256 + tid];
            int m0 = (c.x == b), m1 = (c.y == b), m2 = (c.z == b), m3 = (c.w == b);
            int cnt = m0 + m1 + m2 + m3;
            int wsum = cnt;
#pragma unroll
            for (int off = 16; off > 0; off >>= 1)
                wsum += __shfl_xor_sync(0xffffffffu, wsum, off);
            if (lane == 0) warpcnt[w] = wsum;
            __syncthreads();
            int blocksum = 0;
#pragma unroll
            for (int ww = 0; ww < 8; ww++) blocksum += warpcnt[ww];
            if (total < TOPK && blocksum > 0) {
                // ordered compaction (index order == thread order)
                int incl = cnt;
#pragma unroll
                for (int off = 1; off < 32; off <<= 1) {
                    int v = __shfl_up_sync(0xffffffffu, incl, off);
                    if (lane >= off) incl += v;
                }
                int excl = incl - cnt;
                int wbase = 0;
#pragma unroll
                for (int ww = 0; ww < 8; ww++)
                    if (ww < w) wbase += warpcnt[ww];
                int r = total + wbase + excl;
                int idx = it * 1024 + tid * 4;
                if (m0) { if (r < TOPK) g_top[b * TOPK + r] = idx + 0; r++; }
                if (m1) { if (r < TOPK) g_top[b * TOPK + r] = idx + 1; r++; }
                if (m2) { if (r < TOPK) g_top[b * TOPK + r] = idx + 2; r++; }
                if (m3) { if (r < TOPK) g_top[b * TOPK + r] = idx + 3; r++; }
            }
            total += blocksum;
            __syncthreads();
        }
        if (tid == 0) g_bcnt[b] = total;
    } else {
        // ---- query grouping, one block ----
        __shared__ int qh[NCODE];
        __shared__ int qs[NCODE];
        __shared__ int qoff[NCODE];
        qh[tid] = 0;
        __syncthreads();
        unsigned char my[BATCH / CHUNK];
#pragma unroll
        for (int r = 0; r < BATCH / CHUNK; r++) {
            my[r] = g_qcode[r * CHUNK + tid];
            atomicAdd(&qh[my[r]], 1);
        }
        __syncthreads();
        int v = qh[tid];
        qs[tid] = v;
        __syncthreads();
        for (int off = 1; off < 256; off <<= 1) {
            int tmp = (tid >= off) ? qs[tid - off] : 0;
            __syncthreads();
            qs[tid] += tmp;
            __syncthreads();
        }
        int start = qs[tid] - v;
        g_qbcnt[tid] = v;
        g_qbstart[tid] = start;
        qoff[tid] = start;
        __syncthreads();
#pragma unroll
        for (int r = 0; r < BATCH / CHUNK; r++) {
            int pos = atomicAdd(&qoff[my[r]], 1);
            g_qsorted[pos] = r * CHUNK + tid;
        }
    }
}

// ---------------- K4: grouped attention ----------------
__global__ void k_attn(const float* __restrict__ query,
                       const float* __restrict__ mkeys,
                       const float* __restrict__ mvals) {
    int code = blockIdx.x;
    int qcnt = g_qbcnt[code];
    if ((int)blockIdx.y * 8 >= qcnt) return;
    int tid = threadIdx.x;

    __shared__ int   sidx[TOPK];
    __shared__ float sq[8][HID];
    __shared__ float ssc[8][TOPK];
    __shared__ float swt[8][TOPK];
    __shared__ int   sqi[8];

    int kcnt = g_bcnt[code];
    if (kcnt >= TOPK) {
        if (tid < TOPK) sidx[tid] = g_top[code * TOPK + tid];
    } else if (tid < 32) {
        // exact (distance, index)-ordered fallback; astronomically rare
        int lane = tid;
        int got = 0;
        for (int d = 0; d <= NH && got < TOPK; d++) {
            for (int base = 0; base < CAP; base += 32) {
                int c = g_kcode[base + lane];
                bool hit = (__popc(c ^ code) == d);
                unsigned m = __ballot_sync(0xffffffffu, hit);
                int r = __popc(m & ((1u << lane) - 1u));
                if (hit && got + r < TOPK) sidx[got + r] = base + lane;
                got += __popc(m);
                if (got >= TOPK) break;
            }
        }
    }

    int qbase = g_qbstart[code];
    for (int g = blockIdx.y; g * 8 < qcnt; g += 4) {
        int qs = g * 8;
        int nq = qcnt - qs; if (nq > 8) nq = 8;
        if (tid < nq) sqi[tid] = g_qsorted[qbase + qs + tid];
        __syncthreads();
        for (int i = tid; i < nq * HID; i += 256) {
            int q = i >> 9, h = i & (HID - 1);
            sq[q][h] = query[(size_t)sqi[q] * HID + h];
        }
        __syncthreads();

        if (tid < 128) {
            int sub = tid & 7, kg = tid >> 3;
            const float4* kr0 = (const float4*)(mkeys + (size_t)sidx[kg] * HID);
            const float4* kr1 = (const float4*)(mkeys + (size_t)sidx[kg + 16] * HID);
            float a0[8], a1[8];
#pragma unroll
            for (int q = 0; q < 8; q++) { a0[q] = 0.f; a1[q] = 0.f; }
#pragma unroll
            for (int j = 0; j < 16; j++) {
                int jj = sub + 8 * j;
                float4 k0 = kr0[jj];
                float4 k1 = kr1[jj];
#pragma unroll
                for (int q = 0; q < 8; q++) {
                    float4 qv = ((const float4*)sq[q])[jj];
                    a0[q] += k0.x * qv.x + k0.y * qv.y + k0.z * qv.z + k0.w * qv.w;
                    a1[q] += k1.x * qv.x + k1.y * qv.y + k1.z * qv.z + k1.w * qv.w;
                }
            }
#pragma unroll
            for (int q = 0; q < 8; q++) {
#pragma unroll
                for (int off = 1; off < 8; off <<= 1) {
                    a0[q] += __shfl_xor_sync(0xffffffffu, a0[q], off);
                    a1[q] += __shfl_xor_sync(0xffffffffu, a1[q], off);
                }
            }
            if (sub == 0) {
#pragma unroll
                for (int q = 0; q < 8; q++) {
                    ssc[q][kg]      = a0[q] * 0.04419417382415922f;
                    ssc[q][kg + 16] = a1[q] * 0.04419417382415922f;
                }
            }
        }
        __syncthreads();

        {
            int q = tid >> 5, lane = tid & 31;
            float s = ssc[q][lane];
            float mx = s;
#pragma unroll
            for (int off = 16; off > 0; off >>= 1)
                mx = fmaxf(mx, __shfl_xor_sync(0xffffffffu, mx, off));
            float e = expf(s - mx);
            float sum = e;
#pragma unroll
            for (int off = 16; off > 0; off >>= 1)
                sum += __shfl_xor_sync(0xffffffffu, sum, off);
            swt[q][lane] = e / sum;
        }
        __syncthreads();

        float o0[8], o1[8];
#pragma unroll
        for (int q = 0; q < 8; q++) { o0[q] = 0.f; o1[q] = 0.f; }
#pragma unroll 4
        for (int k = 0; k < TOPK; k++) {
            const float* vr = mvals + (size_t)sidx[k] * HID;
            float v0 = vr[tid];
            float v1 = vr[tid + 256];
#pragma unroll
            for (int q = 0; q < 8; q++) {
                float w = swt[q][k];
                o0[q] += w * v0;
                o1[q] += w * v1;
            }
        }
        for (int q = 0; q < nq; q++) {
            g_memout[(size_t)sqi[q] * HID + tid]       = o0[q];
            g_memout[(size_t)sqi[q] * HID + tid + 256] = o1[q];
        }
        __syncthreads();
    }
}

// ---------------- K5: fused single-pass 3xBF16 tensor-core GEMM ----------------
__device__ __forceinline__ void ldm_x4(uint32_t* r, uint32_t addr) {
    asm volatile("ldmatrix.sync.aligned.m8n8.x4.shared.b16 {%0,%1,%2,%3}, [%4];"
                 : "=r"(r[0]), "=r"(r[1]), "=r"(r[2]), "=r"(r[3]) : "r"(addr));
}
__device__ __forceinline__ void mma_bf16(float* d, const uint32_t* a, uint32_t b0, uint32_t b1) {
    asm volatile("mma.sync.aligned.m16n8k16.row.col.f32.bf16.bf16.f32 "
                 "{%0,%1,%2,%3},{%4,%5,%6,%7},{%8,%9},{%0,%1,%2,%3};"
                 : "+f"(d[0]), "+f"(d[1]), "+f"(d[2]), "+f"(d[3])
                 : "r"(a[0]), "r"(a[1]), "r"(a[2]), "r"(a[3]), "r"(b0), "r"(b1));
}
__device__ __forceinline__ void split2(float x, float y, uint32_t& hi, uint32_t& lo) {
    __nv_bfloat162 h = __float22bfloat162_rn(make_float2(x, y));
    float2 hf = __bfloat1622float2(h);
    __nv_bfloat162 l = __float22bfloat162_rn(make_float2(x - hf.x, y - hf.y));
    hi = *(uint32_t*)&h;
    lo = *(uint32_t*)&l;
}

__global__ void k_gemm_tc(const float* __restrict__ Wt,
                          const float* __restrict__ bias,
                          float* __restrict__ C) {
    const int LDS = 40;
    __shared__ __align__(16) __nv_bfloat16 sAhi[128 * LDS];
    __shared__ __align__(16) __nv_bfloat16 sAlo[128 * LDS];
    __shared__ __align__(16) __nv_bfloat16 sBhi[64 * LDS];
    __shared__ __align__(16) __nv_bfloat16 sBlo[64 * LDS];
    int tid = threadIdx.x;
    int w = tid >> 5, lane = tid & 31;
    int bm = blockIdx.y * 128, bn = blockIdx.x * 64;
    int wm = (w >> 1) * 32, wn = (w & 1) * 32;

    float acc[2][4][4];
#pragma unroll
    for (int mt = 0; mt < 2; mt++)
#pragma unroll
        for (int n8 = 0; n8 < 4; n8++)
#pragma unroll
            for (int i = 0; i < 4; i++) acc[mt][n8][i] = 0.f;

    uint32_t sAhi_u = (uint32_t)__cvta_generic_to_shared(sAhi);
    uint32_t sAlo_u = (uint32_t)__cvta_generic_to_shared(sAlo);
    uint32_t sBhi_u = (uint32_t)__cvta_generic_to_shared(sBhi);
    uint32_t sBlo_u = (uint32_t)__cvta_generic_to_shared(sBlo);
    int lrow = lane & 15, lch = lane >> 4;

    for (int k0 = 0; k0 < HID; k0 += 32) {
        __syncthreads();
#pragma unroll
        for (int t = 0; t < 4; t++) {
            int f = tid + t * 256;
            int row = f >> 3, c4 = f & 7;
            float4 v = *(const float4*)&g_memout[(size_t)(bm + row) * HID + k0 + c4 * 4];
            uint32_t h0, l0, h1, l1;
            split2(v.x, v.y, h0, l0);
            split2(v.z, v.w, h1, l1);
            *(uint2*)(sAhi + row * LDS + c4 * 4) = make_uint2(h0, h1);
            *(uint2*)(sAlo + row * LDS + c4 * 4) = make_uint2(l0, l1);
        }
#pragma unroll
        for (int t = 0; t < 2; t++) {
            int f = tid + t * 256;
            int row = f >> 3, c4 = f & 7;
            float4 v = *(const float4*)&Wt[(size_t)(bn + row) * HID + k0 + c4 * 4];
            uint32_t h0, l0, h1, l1;
            split2(v.x, v.y, h0, l0);
            split2(v.z, v.w, h1, l1);
            *(uint2*)(sBhi + row * LDS + c4 * 4) = make_uint2(h0, h1);
            *(uint2*)(sBlo + row * LDS + c4 * 4) = make_uint2(l0, l1);
        }
        __syncthreads();
#pragma unroll
        for (int ks = 0; ks < 2; ks++) {
            uint32_t ahi[2][4], alo[2][4], bhi[2][4], blo[2][4];
            int aoff = 2 * ((wm + lrow) * LDS + ks * 16 + lch * 8);
            int boff = 2 * ((wn + lrow) * LDS + ks * 16 + lch * 8);
#pragma unroll
            for (int mt = 0; mt < 2; mt++) {
                ldm_x4(ahi[mt], sAhi_u + aoff + 2 * mt * 16 * LDS);
                ldm_x4(alo[mt], sAlo_u + aoff + 2 * mt * 16 * LDS);
            }
#pragma unroll
            for (int nt = 0; nt < 2; nt++) {
                ldm_x4(bhi[nt], sBhi_u + boff + 2 * nt * 16 * LDS);
                ldm_x4(blo[nt], sBlo_u + boff + 2 * nt * 16 * LDS);
            }
#pragma unroll
            for (int mt = 0; mt < 2; mt++)
#pragma unroll
                for (int n8 = 0; n8 < 4; n8++) {
                    int nt = n8 >> 1, hh = n8 & 1;
                    mma_bf16(acc[mt][n8], ahi[mt], bhi[nt][hh], bhi[nt][hh + 2]);
                    mma_bf16(acc[mt][n8], alo[mt], bhi[nt][hh], bhi[nt][hh + 2]);
                    mma_bf16(acc[mt][n8], ahi[mt], blo[nt][hh], blo[nt][hh + 2]);
                }
        }
    }

    int r0 = bm + wm + (lane >> 2);
#pragma unroll
    for (int mt = 0; mt < 2; mt++) {
#pragma unroll
        for (int n8 = 0; n8 < 4; n8++) {
            int col = bn + wn + n8 * 8 + (lane & 3) * 2;
            float b0 = bias[col], b1 = bias[col + 1];
            int r = r0 + mt * 16;
            C[(size_t)r * HID + col]           = acc[mt][n8][0] + b0;
            C[(size_t)r * HID + col + 1]       = acc[mt][n8][1] + b1;
            C[(size_t)(r + 8) * HID + col]     = acc[mt][n8][2] + b0;
            C[(size_t)(r + 8) * HID + col + 1] = acc[mt][n8][3] + b1;
        }
    }
}

// ---------------- launch ----------------
extern "C" void kernel_launch(void* const* d_in, const int* in_sizes, int n_in,
                              void* d_out, int out_size) {
    const float* query = (const float*)d_in[0];
    const float* mkeys = (const float*)d_in[1];
    const float* mvals = (const float*)d_in[2];
    const float* hproj = (const float*)d_in[3];
    const float* outw  = (const float*)d_in[4];
    const float* outb  = (const float*)d_in[5];
    float* out = (float*)d_out;

    unsigned char *qcode, *kcode;
    cudaGetSymbolAddress((void**)&qcode, g_qcode);
    cudaGetSymbolAddress((void**)&kcode, g_kcode);

    k_reduce_w<<<(NH * HID + 255) / 256, 256>>>(hproj);
    k_hash<4><<<CAP / 32, 256>>>(mkeys, kcode);
    k_hash<1><<<BATCH / 8, 256>>>(query, qcode);
    k_select<<<NCODE + 1, 256>>>();
    dim3 agrid(NCODE, 4);
    k_attn<<<agrid, 256>>>(query, mkeys, mvals);
    dim3 ggrid(HID / 64, BATCH / 128);
    k_gemm_tc<<<ggrid, 256>>>(outw, outb, out);
}

// round 9
// speedup vs baseline: 1.1875x; 1.1875x over previous
#include <cuda_runtime.h>
#include <cuda_bf16.h>
#include <cstdint>

#define CAP    65536
#define HID    512
#define NH     8
#define BATCH  2048
#define TOPK   32
#define NCODE  256
#define CHUNK  256

// ---------------- scratch (static device globals; no allocation) ----------------
__device__ float         g_W[NH * HID];
__device__ unsigned char g_qcode[BATCH];
__device__ unsigned char g_kcode[CAP];
__device__ int           g_top[NCODE * TOPK];   // first-32 key indices per code
__device__ int           g_bcnt[NCODE];
__device__ int           g_qbstart[NCODE];
__device__ int           g_qbcnt[NCODE];
__device__ int           g_qsorted[BATCH];
__device__ float         g_memout[BATCH * HID];

// ---------------- K1: W[n][h] = sum_d hp[n][h][d] ----------------
__global__ void k_reduce_w(const float* __restrict__ hp) {
    int i = blockIdx.x * blockDim.x + threadIdx.x;
    if (i < NH * HID) {
        float s = 0.f;
#pragma unroll
        for (int d = 0; d < 16; d++) s += hp[i * 16 + d];
        g_W[i] = s;
    }
}

// ---------------- K2: LSH code, R rows per warp (fp32 exact) ----------------
template <int R>
__global__ void k_hash(const float* __restrict__ X, unsigned char* __restrict__ out) {
    __shared__ float4 sW4[NH * 128];
    int tid = threadIdx.x;
    for (int i = tid; i < NH * 128; i += 256) sW4[i] = ((const float4*)g_W)[i];
    __syncthreads();
    int warp = tid >> 5, lane = tid & 31;
    int r0 = (blockIdx.x * 8 + warp) * R;
    float acc[R][NH];
#pragma unroll
    for (int r = 0; r < R; r++)
#pragma unroll
        for (int n = 0; n < NH; n++) acc[r][n] = 0.f;

#pragma unroll
    for (int i = 0; i < 4; i++) {
        int j = lane + 32 * i;
        float4 xv[R];
#pragma unroll
        for (int r = 0; r < R; r++)
            xv[r] = ((const float4*)(X + (size_t)(r0 + r) * HID))[j];
#pragma unroll
        for (int n = 0; n < NH; n++) {
            float4 wv = sW4[n * 128 + j];
#pragma unroll
            for (int r = 0; r < R; r++)
                acc[r][n] += xv[r].x * wv.x + xv[r].y * wv.y + xv[r].z * wv.z + xv[r].w * wv.w;
        }
    }
#pragma unroll
    for (int r = 0; r < R; r++)
#pragma unroll
        for (int n = 0; n < NH; n++) {
#pragma unroll
            for (int off = 16; off > 0; off >>= 1)
                acc[r][n] += __shfl_xor_sync(0xffffffffu, acc[r][n], off);
        }
    if (lane == 0) {
#pragma unroll
        for (int r = 0; r < R; r++) {
            unsigned c = 0;
#pragma unroll
            for (int n = 0; n < NH; n++)
                if (acc[r][n] > 0.f) c |= (1u << n);
            out[r0 + r] = (unsigned char)c;
        }
    }
}

// ---------------- K3: barrier-light selection ----------------
// blocks 0..255: sweep 64KB codes, 16B/thread/iter; barriers only while total<32.
// block 256:     group the 2048 queries (order within bucket irrelevant).
__global__ void __launch_bounds__(256) k_select(void) {
    int b = blockIdx.x, tid = threadIdx.x;
    if (b < NCODE) {
        int w = tid >> 5, lane = tid & 31;
        __shared__ int warpcnt[8];
        __shared__ int wtot[8];
        unsigned pat = (unsigned)b * 0x01010101u;
        int total = 0;    // block-uniform cumulative (phase A)
        int mycnt = 0;    // thread-local (phase B)
#pragma unroll 1
        for (int it = 0; it < CAP / 4096; it++) {
            uint4 v = ((const uint4*)g_kcode)[it * 256 + tid];  // 16 bytes
            unsigned e0 = __vcmpeq4(v.x, pat);
            unsigned e1 = __vcmpeq4(v.y, pat);
            unsigned e2 = __vcmpeq4(v.z, pat);
            unsigned e3 = __vcmpeq4(v.w, pat);
            int cnt = (__popc(e0) + __popc(e1) + __popc(e2) + __popc(e3)) >> 3;
            if (total < TOPK) {   // block-uniform branch
                int wsum = cnt;
#pragma unroll
                for (int off = 16; off > 0; off >>= 1)
                    wsum += __shfl_xor_sync(0xffffffffu, wsum, off);
                if (lane == 0) warpcnt[w] = wsum;
                __syncthreads();
                int blocksum = 0;
#pragma unroll
                for (int ww = 0; ww < 8; ww++) blocksum += warpcnt[ww];
                if (blocksum > 0) {
                    int incl = cnt;
#pragma unroll
                    for (int off = 1; off < 32; off <<= 1) {
                        int t = __shfl_up_sync(0xffffffffu, incl, off);
                        if (lane >= off) incl += t;
                    }
                    int excl = incl - cnt;
                    int wbase = 0;
#pragma unroll
                    for (int ww = 0; ww < 8; ww++)
                        if (ww < w) wbase += warpcnt[ww];
                    int r = total + wbase + excl;
                    if (cnt > 0 && r < TOPK) {
                        int idx0 = it * 4096 + tid * 16;
                        unsigned e[4] = {e0, e1, e2, e3};
#pragma unroll
                        for (int k = 0; k < 4; k++)
#pragma unroll
                            for (int j = 0; j < 4; j++)
                                if ((e[k] >> (8 * j)) & 1u) {
                                    if (r < TOPK) g_top[b * TOPK + r] = idx0 + k * 4 + j;
                                    r++;
                                }
                    }
                }
                total += blocksum;
                __syncthreads();
            } else {
                mycnt += cnt;     // barrier-free tail
            }
        }
        // final block reduce of mycnt
        int wsum = mycnt;
#pragma unroll
        for (int off = 16; off > 0; off >>= 1)
            wsum += __shfl_xor_sync(0xffffffffu, wsum, off);
        if (lane == 0) wtot[w] = wsum;
        __syncthreads();
        if (tid == 0) {
            int t = total;
#pragma unroll
            for (int ww = 0; ww < 8; ww++) t += wtot[ww];
            g_bcnt[b] = t;
        }
    } else {
        // ---- query grouping, one block ----
        __shared__ int qh[NCODE];
        __shared__ int qs[NCODE];
        __shared__ int qoff[NCODE];
        qh[tid] = 0;
        __syncthreads();
        unsigned char my[BATCH / CHUNK];
#pragma unroll
        for (int r = 0; r < BATCH / CHUNK; r++) {
            my[r] = g_qcode[r * CHUNK + tid];
            atomicAdd(&qh[my[r]], 1);
        }
        __syncthreads();
        int v = qh[tid];
        qs[tid] = v;
        __syncthreads();
        for (int off = 1; off < 256; off <<= 1) {
            int tmp = (tid >= off) ? qs[tid - off] : 0;
            __syncthreads();
            qs[tid] += tmp;
            __syncthreads();
        }
        int start = qs[tid] - v;
        g_qbcnt[tid] = v;
        g_qbstart[tid] = start;
        qoff[tid] = start;
        __syncthreads();
#pragma unroll
        for (int r = 0; r < BATCH / CHUNK; r++) {
            int pos = atomicAdd(&qoff[my[r]], 1);
            g_qsorted[pos] = r * CHUNK + tid;
        }
    }
}

// ---------------- K4: grouped attention ----------------
__global__ void k_attn(const float* __restrict__ query,
                       const float* __restrict__ mkeys,
                       const float* __restrict__ mvals) {
    int code = blockIdx.x;
    int qcnt = g_qbcnt[code];
    if ((int)blockIdx.y * 8 >= qcnt) return;
    int tid = threadIdx.x;

    __shared__ int   sidx[TOPK];
    __shared__ float sq[8][HID];
    __shared__ float ssc[8][TOPK];
    __shared__ float swt[8][TOPK];
    __shared__ int   sqi[8];

    int kcnt = g_bcnt[code];
    if (kcnt >= TOPK) {
        if (tid < TOPK) sidx[tid] = g_top[code * TOPK + tid];
    } else if (tid < 32) {
        // exact (distance, index)-ordered fallback; astronomically rare
        int lane = tid;
        int got = 0;
        for (int d = 0; d <= NH && got < TOPK; d++) {
            for (int base = 0; base < CAP; base += 32) {
                int c = g_kcode[base + lane];
                bool hit = (__popc(c ^ code) == d);
                unsigned m = __ballot_sync(0xffffffffu, hit);
                int r = __popc(m & ((1u << lane) - 1u));
                if (hit && got + r < TOPK) sidx[got + r] = base + lane;
                got += __popc(m);
                if (got >= TOPK) break;
            }
        }
    }

    int qbase = g_qbstart[code];
    for (int g = blockIdx.y; g * 8 < qcnt; g += 4) {
        int qs = g * 8;
        int nq = qcnt - qs; if (nq > 8) nq = 8;
        if (tid < nq) sqi[tid] = g_qsorted[qbase + qs + tid];
        __syncthreads();
        for (int i = tid; i < nq * HID; i += 256) {
            int q = i >> 9, h = i & (HID - 1);
            sq[q][h] = query[(size_t)sqi[q] * HID + h];
        }
        __syncthreads();

        if (tid < 128) {
            int sub = tid & 7, kg = tid >> 3;
            const float4* kr0 = (const float4*)(mkeys + (size_t)sidx[kg] * HID);
            const float4* kr1 = (const float4*)(mkeys + (size_t)sidx[kg + 16] * HID);
            float a0[8], a1[8];
#pragma unroll
            for (int q = 0; q < 8; q++) { a0[q] = 0.f; a1[q] = 0.f; }
#pragma unroll
            for (int j = 0; j < 16; j++) {
                int jj = sub + 8 * j;
                float4 k0 = kr0[jj];
                float4 k1 = kr1[jj];
#pragma unroll
                for (int q = 0; q < 8; q++) {
                    float4 qv = ((const float4*)sq[q])[jj];
                    a0[q] += k0.x * qv.x + k0.y * qv.y + k0.z * qv.z + k0.w * qv.w;
                    a1[q] += k1.x * qv.x + k1.y * qv.y + k1.z * qv.z + k1.w * qv.w;
                }
            }
#pragma unroll
            for (int q = 0; q < 8; q++) {
#pragma unroll
                for (int off = 1; off < 8; off <<= 1) {
                    a0[q] += __shfl_xor_sync(0xffffffffu, a0[q], off);
                    a1[q] += __shfl_xor_sync(0xffffffffu, a1[q], off);
                }
            }
            if (sub == 0) {
#pragma unroll
                for (int q = 0; q < 8; q++) {
                    ssc[q][kg]      = a0[q] * 0.04419417382415922f;
                    ssc[q][kg + 16] = a1[q] * 0.04419417382415922f;
                }
            }
        }
        __syncthreads();

        {
            int q = tid >> 5, lane = tid & 31;
            float s = ssc[q][lane];
            float mx = s;
#pragma unroll
            for (int off = 16; off > 0; off >>= 1)
                mx = fmaxf(mx, __shfl_xor_sync(0xffffffffu, mx, off));
            float e = expf(s - mx);
            float sum = e;
#pragma unroll
            for (int off = 16; off > 0; off >>= 1)
                sum += __shfl_xor_sync(0xffffffffu, sum, off);
            swt[q][lane] = e / sum;
        }
        __syncthreads();

        float o0[8], o1[8];
#pragma unroll
        for (int q = 0; q < 8; q++) { o0[q] = 0.f; o1[q] = 0.f; }
#pragma unroll 4
        for (int k = 0; k < TOPK; k++) {
            const float* vr = mvals + (size_t)sidx[k] * HID;
            float v0 = vr[tid];
            float v1 = vr[tid + 256];
#pragma unroll
            for (int q = 0; q < 8; q++) {
                float w = swt[q][k];
                o0[q] += w * v0;
                o1[q] += w * v1;
            }
        }
        for (int q = 0; q < nq; q++) {
            g_memout[(size_t)sqi[q] * HID + tid]       = o0[q];
            g_memout[(size_t)sqi[q] * HID + tid + 256] = o1[q];
        }
        __syncthreads();
    }
}

// ---------------- K5: fused single-pass 3xBF16 tensor-core GEMM ----------------
__device__ __forceinline__ void ldm_x4(uint32_t* r, uint32_t addr) {
    asm volatile("ldmatrix.sync.aligned.m8n8.x4.shared.b16 {%0,%1,%2,%3}, [%4];"
                 : "=r"(r[0]), "=r"(r[1]), "=r"(r[2]), "=r"(r[3]) : "r"(addr));
}
__device__ __forceinline__ void mma_bf16(float* d, const uint32_t* a, uint32_t b0, uint32_t b1) {
    asm volatile("mma.sync.aligned.m16n8k16.row.col.f32.bf16.bf16.f32 "
                 "{%0,%1,%2,%3},{%4,%5,%6,%7},{%8,%9},{%0,%1,%2,%3};"
                 : "+f"(d[0]), "+f"(d[1]), "+f"(d[2]), "+f"(d[3])
                 : "r"(a[0]), "r"(a[1]), "r"(a[2]), "r"(a[3]), "r"(b0), "r"(b1));
}
__device__ __forceinline__ void split2(float x, float y, uint32_t& hi, uint32_t& lo) {
    __nv_bfloat162 h = __float22bfloat162_rn(make_float2(x, y));
    float2 hf = __bfloat1622float2(h);
    __nv_bfloat162 l = __float22bfloat162_rn(make_float2(x - hf.x, y - hf.y));
    hi = *(uint32_t*)&h;
    lo = *(uint32_t*)&l;
}

__global__ void k_gemm_tc(const float* __restrict__ Wt,
                          const float* __restrict__ bias,
                          float* __restrict__ C) {
    const int LDS = 40;
    __shared__ __align__(16) __nv_bfloat16 sAhi[128 * LDS];
    __shared__ __align__(16) __nv_bfloat16 sAlo[128 * LDS];
    __shared__ __align__(16) __nv_bfloat16 sBhi[64 * LDS];
    __shared__ __align__(16) __nv_bfloat16 sBlo[64 * LDS];
    int tid = threadIdx.x;
    int w = tid >> 5, lane = tid & 31;
    int bm = blockIdx.y * 128, bn = blockIdx.x * 64;
    int wm = (w >> 1) * 32, wn = (w & 1) * 32;

    float acc[2][4][4];
#pragma unroll
    for (int mt = 0; mt < 2; mt++)
#pragma unroll
        for (int n8 = 0; n8 < 4; n8++)
#pragma unroll
            for (int i = 0; i < 4; i++) acc[mt][n8][i] = 0.f;

    uint32_t sAhi_u = (uint32_t)__cvta_generic_to_shared(sAhi);
    uint32_t sAlo_u = (uint32_t)__cvta_generic_to_shared(sAlo);
    uint32_t sBhi_u = (uint32_t)__cvta_generic_to_shared(sBhi);
    uint32_t sBlo_u = (uint32_t)__cvta_generic_to_shared(sBlo);
    int lrow = lane & 15, lch = lane >> 4;

    for (int k0 = 0; k0 < HID; k0 += 32) {
        __syncthreads();
#pragma unroll
        for (int t = 0; t < 4; t++) {
            int f = tid + t * 256;
            int row = f >> 3, c4 = f & 7;
            float4 v = *(const float4*)&g_memout[(size_t)(bm + row) * HID + k0 + c4 * 4];
            uint32_t h0, l0, h1, l1;
            split2(v.x, v.y, h0, l0);
            split2(v.z, v.w, h1, l1);
            *(uint2*)(sAhi + row * LDS + c4 * 4) = make_uint2(h0, h1);
            *(uint2*)(sAlo + row * LDS + c4 * 4) = make_uint2(l0, l1);
        }
#pragma unroll
        for (int t = 0; t < 2; t++) {
            int f = tid + t * 256;
            int row = f >> 3, c4 = f & 7;
            float4 v = *(const float4*)&Wt[(size_t)(bn + row) * HID + k0 + c4 * 4];
            uint32_t h0, l0, h1, l1;
            split2(v.x, v.y, h0, l0);
            split2(v.z, v.w, h1, l1);
            *(uint2*)(sBhi + row * LDS + c4 * 4) = make_uint2(h0, h1);
            *(uint2*)(sBlo + row * LDS + c4 * 4) = make_uint2(l0, l1);
        }
        __syncthreads();
#pragma unroll
        for (int ks = 0; ks < 2; ks++) {
            uint32_t ahi[2][4], alo[2][4], bhi[2][4], blo[2][4];
            int aoff = 2 * ((wm + lrow) * LDS + ks * 16 + lch * 8);
            int boff = 2 * ((wn + lrow) * LDS + ks * 16 + lch * 8);
#pragma unroll
            for (int mt = 0; mt < 2; mt++) {
                ldm_x4(ahi[mt], sAhi_u + aoff + 2 * mt * 16 * LDS);
                ldm_x4(alo[mt], sAlo_u + aoff + 2 * mt * 16 * LDS);
            }
#pragma unroll
            for (int nt = 0; nt < 2; nt++) {
                ldm_x4(bhi[nt], sBhi_u + boff + 2 * nt * 16 * LDS);
                ldm_x4(blo[nt], sBlo_u + boff + 2 * nt * 16 * LDS);
            }
#pragma unroll
            for (int mt = 0; mt < 2; mt++)
#pragma unroll
                for (int n8 = 0; n8 < 4; n8++) {
                    int nt = n8 >> 1, hh = n8 & 1;
                    mma_bf16(acc[mt][n8], ahi[mt], bhi[nt][hh], bhi[nt][hh + 2]);
                    mma_bf16(acc[mt][n8], alo[mt], bhi[nt][hh], bhi[nt][hh + 2]);
                    mma_bf16(acc[mt][n8], ahi[mt], blo[nt][hh], blo[nt][hh + 2]);
                }
        }
    }

    int r0 = bm + wm + (lane >> 2);
#pragma unroll
    for (int mt = 0; mt < 2; mt++) {
#pragma unroll
        for (int n8 = 0; n8 < 4; n8++) {
            int col = bn + wn + n8 * 8 + (lane & 3) * 2;
            float b0 = bias[col], b1 = bias[col + 1];
            int r = r0 + mt * 16;
            C[(size_t)r * HID + col]           = acc[mt][n8][0] + b0;
            C[(size_t)r * HID + col + 1]       = acc[mt][n8][1] + b1;
            C[(size_t)(r + 8) * HID + col]     = acc[mt][n8][2] + b0;
            C[(size_t)(r + 8) * HID + col + 1] = acc[mt][n8][3] + b1;
        }
    }
}

// ---------------- launch ----------------
extern "C" void kernel_launch(void* const* d_in, const int* in_sizes, int n_in,
                              void* d_out, int out_size) {
    const float* query = (const float*)d_in[0];
    const float* mkeys = (const float*)d_in[1];
    const float* mvals = (const float*)d_in[2];
    const float* hproj = (const float*)d_in[3];
    const float* outw  = (const float*)d_in[4];
    const float* outb  = (const float*)d_in[5];
    float* out = (float*)d_out;

    unsigned char *qcode, *kcode;
    cudaGetSymbolAddress((void**)&qcode, g_qcode);
    cudaGetSymbolAddress((void**)&kcode, g_kcode);

    k_reduce_w<<<(NH * HID + 255) / 256, 256>>>(hproj);
    k_hash<4><<<CAP / 32, 256>>>(mkeys, kcode);
    k_hash<1><<<BATCH / 8, 256>>>(query, qcode);
    k_select<<<NCODE + 1, 256>>>();
    dim3 agrid(NCODE, 4);
    k_attn<<<agrid, 256>>>(query, mkeys, mvals);
    dim3 ggrid(HID / 64, BATCH / 128);
    k_gemm_tc<<<ggrid, 256>>>(outw, outb, out);
}

// round 10
// speedup vs baseline: 1.2360x; 1.0409x over previous
#include <cuda_runtime.h>
#include <cuda_bf16.h>
#include <cstdint>

#define CAP    65536
#define HID    512
#define NH     8
#define BATCH  2048
#define TOPK   32
#define NCODE  256

// ---------------- scratch (static device globals; no allocation) ----------------
__device__ float         g_W[NH * HID];
__device__ unsigned char g_qcode[BATCH];
__device__ unsigned char g_kcode[CAP];
__device__ int           g_top[NCODE * TOPK];   // first-32 key indices per code
__device__ int           g_bcnt[NCODE];
__device__ int           g_qbstart[NCODE];
__device__ int           g_qbcnt[NCODE];
__device__ int           g_qsorted[BATCH];
__device__ float         g_memout[BATCH * HID];

// ---------------- K1: W[n][h] = sum_d hp[n][h][d] ----------------
__global__ void k_reduce_w(const float* __restrict__ hp) {
    int i = blockIdx.x * blockDim.x + threadIdx.x;
    if (i < NH * HID) {
        float s = 0.f;
#pragma unroll
        for (int d = 0; d < 16; d++) s += hp[i * 16 + d];
        g_W[i] = s;
    }
}

// ---------------- K2: LSH code, R rows per warp (fp32 exact) ----------------
template <int R>
__global__ void k_hash(const float* __restrict__ X, unsigned char* __restrict__ out) {
    __shared__ float4 sW4[NH * 128];
    int tid = threadIdx.x;
    for (int i = tid; i < NH * 128; i += 256) sW4[i] = ((const float4*)g_W)[i];
    __syncthreads();
    int warp = tid >> 5, lane = tid & 31;
    int r0 = (blockIdx.x * 8 + warp) * R;
    float acc[R][NH];
#pragma unroll
    for (int r = 0; r < R; r++)
#pragma unroll
        for (int n = 0; n < NH; n++) acc[r][n] = 0.f;

#pragma unroll
    for (int i = 0; i < 4; i++) {
        int j = lane + 32 * i;
        float4 xv[R];
#pragma unroll
        for (int r = 0; r < R; r++)
            xv[r] = ((const float4*)(X + (size_t)(r0 + r) * HID))[j];
#pragma unroll
        for (int n = 0; n < NH; n++) {
            float4 wv = sW4[n * 128 + j];
#pragma unroll
            for (int r = 0; r < R; r++)
                acc[r][n] += xv[r].x * wv.x + xv[r].y * wv.y + xv[r].z * wv.z + xv[r].w * wv.w;
        }
    }
#pragma unroll
    for (int r = 0; r < R; r++)
#pragma unroll
        for (int n = 0; n < NH; n++) {
#pragma unroll
            for (int off = 16; off > 0; off >>= 1)
                acc[r][n] += __shfl_xor_sync(0xffffffffu, acc[r][n], off);
        }
    if (lane == 0) {
#pragma unroll
        for (int r = 0; r < R; r++) {
            unsigned c = 0;
#pragma unroll
            for (int n = 0; n < NH; n++)
                if (acc[r][n] > 0.f) c |= (1u << n);
            out[r0 + r] = (unsigned char)c;
        }
    }
}

// ---------------- K3: selection, MLP-aware ----------------
// blocks 0..255 (512 thr): 2 heavy iterations (compaction), then 6 unrolled
//                          count-only iterations with 6 loads in flight.
// block 256: group the 2048 queries (order within bucket irrelevant).
__device__ __forceinline__ int heavy_iter(int it, int b, unsigned pat, int total,
                                          int w, int lane, int tid, int* warpcnt) {
    uint4 v = ((const uint4*)g_kcode)[it * 512 + tid];
    unsigned e0 = __vcmpeq4(v.x, pat);
    unsigned e1 = __vcmpeq4(v.y, pat);
    unsigned e2 = __vcmpeq4(v.z, pat);
    unsigned e3 = __vcmpeq4(v.w, pat);
    int cnt = (__popc(e0) + __popc(e1) + __popc(e2) + __popc(e3)) >> 3;
    int wsum = cnt;
#pragma unroll
    for (int off = 16; off > 0; off >>= 1)
        wsum += __shfl_xor_sync(0xffffffffu, wsum, off);
    if (lane == 0) warpcnt[w] = wsum;
    __syncthreads();
    int blocksum = 0;
#pragma unroll
    for (int ww = 0; ww < 16; ww++) blocksum += warpcnt[ww];
    if (blocksum > 0 && total < TOPK) {
        int incl = cnt;
#pragma unroll
        for (int off = 1; off < 32; off <<= 1) {
            int t = __shfl_up_sync(0xffffffffu, incl, off);
            if (lane >= off) incl += t;
        }
        int excl = incl - cnt;
        int wbase = 0;
#pragma unroll
        for (int ww = 0; ww < 16; ww++)
            if (ww < w) wbase += warpcnt[ww];
        int r = total + wbase + excl;
        if (cnt > 0 && r < TOPK) {
            int idx0 = it * 8192 + tid * 16;
            unsigned e[4] = {e0, e1, e2, e3};
#pragma unroll
            for (int k = 0; k < 4; k++)
#pragma unroll
                for (int j = 0; j < 4; j++)
                    if ((e[k] >> (8 * j)) & 1u) {
                        if (r < TOPK) g_top[b * TOPK + r] = idx0 + k * 4 + j;
                        r++;
                    }
        }
    }
    __syncthreads();
    return blocksum;
}

__global__ void __launch_bounds__(512) k_select(void) {
    int b = blockIdx.x, tid = threadIdx.x;
    if (b < NCODE) {
        int w = tid >> 5, lane = tid & 31;
        __shared__ int warpcnt[16];
        __shared__ int wtot[16];
        unsigned pat = (unsigned)b * 0x01010101u;
        int total = 0;
        // phase A: exactly 2 heavy iterations (covers 16384 keys; E[matches]=64)
        total += heavy_iter(0, b, pat, total, w, lane, tid, warpcnt);
        total += heavy_iter(1, b, pat, total, w, lane, tid, warpcnt);
        int mycnt = 0;
        if (total >= TOPK) {
            // fast path: 6 fully-unrolled count-only iterations (MLP=6)
#pragma unroll
            for (int it = 2; it < 8; it++) {
                uint4 v = ((const uint4*)g_kcode)[it * 512 + tid];
                mycnt += (__popc(__vcmpeq4(v.x, pat)) + __popc(__vcmpeq4(v.y, pat)) +
                          __popc(__vcmpeq4(v.z, pat)) + __popc(__vcmpeq4(v.w, pat))) >> 3;
            }
        } else {
            // rare exact path: keep compacting in index order
#pragma unroll 1
            for (int it = 2; it < 8; it++)
                total += heavy_iter(it, b, pat, total, w, lane, tid, warpcnt);
        }
        int wsum = mycnt;
#pragma unroll
        for (int off = 16; off > 0; off >>= 1)
            wsum += __shfl_xor_sync(0xffffffffu, wsum, off);
        if (lane == 0) wtot[w] = wsum;
        __syncthreads();
        if (tid == 0) {
            int t = total;
#pragma unroll
            for (int ww = 0; ww < 16; ww++) t += wtot[ww];
            g_bcnt[b] = t;
        }
    } else {
        // ---- query grouping, one block of 512 ----
        __shared__ int qh[NCODE];
        __shared__ int qs2[NCODE];
        __shared__ int qoff[NCODE];
        if (tid < 256) qh[tid] = 0;
        __syncthreads();
        unsigned char my[BATCH / 512];
#pragma unroll
        for (int r = 0; r < BATCH / 512; r++) {
            my[r] = g_qcode[r * 512 + tid];
            atomicAdd(&qh[my[r]], 1);
        }
        __syncthreads();
        int v = 0;
        if (tid < 256) { v = qh[tid]; qs2[tid] = v; }
        __syncthreads();
        for (int off = 1; off < 256; off <<= 1) {
            int tmp = (tid < 256 && tid >= off) ? qs2[tid - off] : 0;
            __syncthreads();
            if (tid < 256) qs2[tid] += tmp;
            __syncthreads();
        }
        if (tid < 256) {
            int start = qs2[tid] - v;
            g_qbcnt[tid] = v;
            g_qbstart[tid] = start;
            qoff[tid] = start;
        }
        __syncthreads();
#pragma unroll
        for (int r = 0; r < BATCH / 512; r++) {
            int pos = atomicAdd(&qoff[my[r]], 1);
            g_qsorted[pos] = r * 512 + tid;
        }
    }
}

// ---------------- K4: grouped attention ----------------
__global__ void k_attn(const float* __restrict__ query,
                       const float* __restrict__ mkeys,
                       const float* __restrict__ mvals) {
    int code = blockIdx.x;
    int qcnt = g_qbcnt[code];
    if ((int)blockIdx.y * 8 >= qcnt) return;
    int tid = threadIdx.x;

    __shared__ int   sidx[TOPK];
    __shared__ float sq[8][HID];
    __shared__ float ssc[8][TOPK];
    __shared__ float swt[8][TOPK];
    __shared__ int   sqi[8];

    int kcnt = g_bcnt[code];
    if (kcnt >= TOPK) {
        if (tid < TOPK) sidx[tid] = g_top[code * TOPK + tid];
    } else if (tid < 32) {
        // exact (distance, index)-ordered fallback; astronomically rare
        int lane = tid;
        int got = 0;
        for (int d = 0; d <= NH && got < TOPK; d++) {
            for (int base = 0; base < CAP; base += 32) {
                int c = g_kcode[base + lane];
                bool hit = (__popc(c ^ code) == d);
                unsigned m = __ballot_sync(0xffffffffu, hit);
                int r = __popc(m & ((1u << lane) - 1u));
                if (hit && got + r < TOPK) sidx[got + r] = base + lane;
                got += __popc(m);
                if (got >= TOPK) break;
            }
        }
    }

    int qbase = g_qbstart[code];
    for (int g = blockIdx.y; g * 8 < qcnt; g += 4) {
        int qs = g * 8;
        int nq = qcnt - qs; if (nq > 8) nq = 8;
        if (tid < nq) sqi[tid] = g_qsorted[qbase + qs + tid];
        __syncthreads();
        for (int i = tid; i < nq * HID; i += 256) {
            int q = i >> 9, h = i & (HID - 1);
            sq[q][h] = query[(size_t)sqi[q] * HID + h];
        }
        __syncthreads();

        if (tid < 128) {
            int sub = tid & 7, kg = tid >> 3;
            const float4* kr0 = (const float4*)(mkeys + (size_t)sidx[kg] * HID);
            const float4* kr1 = (const float4*)(mkeys + (size_t)sidx[kg + 16] * HID);
            float a0[8], a1[8];
#pragma unroll
            for (int q = 0; q < 8; q++) { a0[q] = 0.f; a1[q] = 0.f; }
#pragma unroll
            for (int j = 0; j < 16; j++) {
                int jj = sub + 8 * j;
                float4 k0 = kr0[jj];
                float4 k1 = kr1[jj];
#pragma unroll
                for (int q = 0; q < 8; q++) {
                    float4 qv = ((const float4*)sq[q])[jj];
                    a0[q] += k0.x * qv.x + k0.y * qv.y + k0.z * qv.z + k0.w * qv.w;
                    a1[q] += k1.x * qv.x + k1.y * qv.y + k1.z * qv.z + k1.w * qv.w;
                }
            }
#pragma unroll
            for (int q = 0; q < 8; q++) {
#pragma unroll
                for (int off = 1; off < 8; off <<= 1) {
                    a0[q] += __shfl_xor_sync(0xffffffffu, a0[q], off);
                    a1[q] += __shfl_xor_sync(0xffffffffu, a1[q], off);
                }
            }
            if (sub == 0) {
#pragma unroll
                for (int q = 0; q < 8; q++) {
                    ssc[q][kg]      = a0[q] * 0.04419417382415922f;
                    ssc[q][kg + 16] = a1[q] * 0.04419417382415922f;
                }
            }
        }
        __syncthreads();

        {
            int q = tid >> 5, lane = tid & 31;
            float s = ssc[q][lane];
            float mx = s;
#pragma unroll
            for (int off = 16; off > 0; off >>= 1)
                mx = fmaxf(mx, __shfl_xor_sync(0xffffffffu, mx, off));
            float e = expf(s - mx);
            float sum = e;
#pragma unroll
            for (int off = 16; off > 0; off >>= 1)
                sum += __shfl_xor_sync(0xffffffffu, sum, off);
            swt[q][lane] = e / sum;
        }
        __syncthreads();

        float o0[8], o1[8];
#pragma unroll
        for (int q = 0; q < 8; q++) { o0[q] = 0.f; o1[q] = 0.f; }
#pragma unroll 4
        for (int k = 0; k < TOPK; k++) {
            const float* vr = mvals + (size_t)sidx[k] * HID;
            float v0 = vr[tid];
            float v1 = vr[tid + 256];
#pragma unroll
            for (int q = 0; q < 8; q++) {
                float w = swt[q][k];
                o0[q] += w * v0;
                o1[q] += w * v1;
            }
        }
        for (int q = 0; q < nq; q++) {
            g_memout[(size_t)sqi[q] * HID + tid]       = o0[q];
            g_memout[(size_t)sqi[q] * HID + tid + 256] = o1[q];
        }
        __syncthreads();
    }
}

// ---------------- K5: fused single-pass 3xBF16 tensor-core GEMM ----------------
__device__ __forceinline__ void ldm_x4(uint32_t* r, uint32_t addr) {
    asm volatile("ldmatrix.sync.aligned.m8n8.x4.shared.b16 {%0,%1,%2,%3}, [%4];"
                 : "=r"(r[0]), "=r"(r[1]), "=r"(r[2]), "=r"(r[3]) : "r"(addr));
}
__device__ __forceinline__ void mma_bf16(float* d, const uint32_t* a, uint32_t b0, uint32_t b1) {
    asm volatile("mma.sync.aligned.m16n8k16.row.col.f32.bf16.bf16.f32 "
                 "{%0,%1,%2,%3},{%4,%5,%6,%7},{%8,%9},{%0,%1,%2,%3};"
                 : "+f"(d[0]), "+f"(d[1]), "+f"(d[2]), "+f"(d[3])
                 : "r"(a[0]), "r"(a[1]), "r"(a[2]), "r"(a[3]), "r"(b0), "r"(b1));
}
__device__ __forceinline__ void split2(float x, float y, uint32_t& hi, uint32_t& lo) {
    __nv_bfloat162 h = __float22bfloat162_rn(make_float2(x, y));
    float2 hf = __bfloat1622float2(h);
    __nv_bfloat162 l = __float22bfloat162_rn(make_float2(x - hf.x, y - hf.y));
    hi = *(uint32_t*)&h;
    lo = *(uint32_t*)&l;
}

__global__ void k_gemm_tc(const float* __restrict__ Wt,
                          const float* __restrict__ bias,
                          float* __restrict__ C) {
    const int LDS = 40;
    __shared__ __align__(16) __nv_bfloat16 sAhi[128 * LDS];
    __shared__ __align__(16) __nv_bfloat16 sAlo[128 * LDS];
    __shared__ __align__(16) __nv_bfloat16 sBhi[64 * LDS];
    __shared__ __align__(16) __nv_bfloat16 sBlo[64 * LDS];
    int tid = threadIdx.x;
    int w = tid >> 5, lane = tid & 31;
    int bm = blockIdx.y * 128, bn = blockIdx.x * 64;
    int wm = (w >> 1) * 32, wn = (w & 1) * 32;

    float acc[2][4][4];
#pragma unroll
    for (int mt = 0; mt < 2; mt++)
#pragma unroll
        for (int n8 = 0; n8 < 4; n8++)
#pragma unroll
            for (int i = 0; i < 4; i++) acc[mt][n8][i] = 0.f;

    uint32_t sAhi_u = (uint32_t)__cvta_generic_to_shared(sAhi);
    uint32_t sAlo_u = (uint32_t)__cvta_generic_to_shared(sAlo);
    uint32_t sBhi_u = (uint32_t)__cvta_generic_to_shared(sBhi);
    uint32_t sBlo_u = (uint32_t)__cvta_generic_to_shared(sBlo);
    int lrow = lane & 15, lch = lane >> 4;

    for (int k0 = 0; k0 < HID; k0 += 32) {
        __syncthreads();
#pragma unroll
        for (int t = 0; t < 4; t++) {
            int f = tid + t * 256;
            int row = f >> 3, c4 = f & 7;
            float4 v = *(const float4*)&g_memout[(size_t)(bm + row) * HID + k0 + c4 * 4];
            uint32_t h0, l0, h1, l1;
            split2(v.x, v.y, h0, l0);
            split2(v.z, v.w, h1, l1);
            *(uint2*)(sAhi + row * LDS + c4 * 4) = make_uint2(h0, h1);
            *(uint2*)(sAlo + row * LDS + c4 * 4) = make_uint2(l0, l1);
        }
#pragma unroll
        for (int t = 0; t < 2; t++) {
            int f = tid + t * 256;
            int row = f >> 3, c4 = f & 7;
            float4 v = *(const float4*)&Wt[(size_t)(bn + row) * HID + k0 + c4 * 4];
            uint32_t h0, l0, h1, l1;
            split2(v.x, v.y, h0, l0);
            split2(v.z, v.w, h1, l1);
            *(uint2*)(sBhi + row * LDS + c4 * 4) = make_uint2(h0, h1);
            *(uint2*)(sBlo + row * LDS + c4 * 4) = make_uint2(l0, l1);
        }
        __syncthreads();
#pragma unroll
        for (int ks = 0; ks < 2; ks++) {
            uint32_t ahi[2][4], alo[2][4], bhi[2][4], blo[2][4];
            int aoff = 2 * ((wm + lrow) * LDS + ks * 16 + lch * 8);
            int boff = 2 * ((wn + lrow) * LDS + ks * 16 + lch * 8);
#pragma unroll
            for (int mt = 0; mt < 2; mt++) {
                ldm_x4(ahi[mt], sAhi_u + aoff + 2 * mt * 16 * LDS);
                ldm_x4(alo[mt], sAlo_u + aoff + 2 * mt * 16 * LDS);
            }
#pragma unroll
            for (int nt = 0; nt < 2; nt++) {
                ldm_x4(bhi[nt], sBhi_u + boff + 2 * nt * 16 * LDS);
                ldm_x4(blo[nt], sBlo_u + boff + 2 * nt * 16 * LDS);
            }
#pragma unroll
            for (int mt = 0; mt < 2; mt++)
#pragma unroll
                for (int n8 = 0; n8 < 4; n8++) {
                    int nt = n8 >> 1, hh = n8 & 1;
                    mma_bf16(acc[mt][n8], ahi[mt], bhi[nt][hh], bhi[nt][hh + 2]);
                    mma_bf16(acc[mt][n8], alo[mt], bhi[nt][hh], bhi[nt][hh + 2]);
                    mma_bf16(acc[mt][n8], ahi[mt], blo[nt][hh], blo[nt][hh + 2]);
                }
        }
    }

    int r0 = bm + wm + (lane >> 2);
#pragma unroll
    for (int mt = 0; mt < 2; mt++) {
#pragma unroll
        for (int n8 = 0; n8 < 4; n8++) {
            int col = bn + wn + n8 * 8 + (lane & 3) * 2;
            float b0 = bias[col], b1 = bias[col + 1];
            int r = r0 + mt * 16;
            C[(size_t)r * HID + col]           = acc[mt][n8][0] + b0;
            C[(size_t)r * HID + col + 1]       = acc[mt][n8][1] + b1;
            C[(size_t)(r + 8) * HID + col]     = acc[mt][n8][2] + b0;
            C[(size_t)(r + 8) * HID + col + 1] = acc[mt][n8][3] + b1;
        }
    }
}

// ---------------- launch ----------------
extern "C" void kernel_launch(void* const* d_in, const int* in_sizes, int n_in,
                              void* d_out, int out_size) {
    const float* query = (const float*)d_in[0];
    const float* mkeys = (const float*)d_in[1];
    const float* mvals = (const float*)d_in[2];
    const float* hproj = (const float*)d_in[3];
    const float* outw  = (const float*)d_in[4];
    const float* outb  = (const float*)d_in[5];
    float* out = (float*)d_out;

    unsigned char *qcode, *kcode;
    cudaGetSymbolAddress((void**)&qcode, g_qcode);
    cudaGetSymbolAddress((void**)&kcode, g_kcode);

    k_reduce_w<<<(NH * HID + 255) / 256, 256>>>(hproj);
    k_hash<4><<<CAP / 32, 256>>>(mkeys, kcode);
    k_hash<1><<<BATCH / 8, 256>>>(query, qcode);
    k_select<<<NCODE + 1, 512>>>();
    dim3 agrid(NCODE, 4);
    k_attn<<<agrid, 256>>>(query, mkeys, mvals);
    dim3 ggrid(HID / 64, BATCH / 128);
    k_gemm_tc<<<ggrid, 256>>>(outw, outb, out);
}

// round 11
// speedup vs baseline: 1.2507x; 1.0119x over previous
#include <cuda_runtime.h>
#include <cuda_bf16.h>
#include <cstdint>

#define CAP    65536
#define HID    512
#define NH     8
#define BATCH  2048
#define TOPK   32
#define NCODE  256

// ---------------- scratch (static device globals; no allocation) ----------------
__device__ float         g_W[NH * HID];
__device__ unsigned char g_qcode[BATCH];
__device__ unsigned char g_kcode[CAP];
__device__ int           g_top[NCODE * TOPK];   // first-32 key indices per code
__device__ int           g_bcnt[NCODE];
__device__ int           g_qbstart[NCODE];
__device__ int           g_qbcnt[NCODE];
__device__ int           g_qsorted[BATCH];
__device__ float         g_memout[BATCH * HID];

// ---------------- K1: W[n][h] = sum_d hp[n][h][d] ----------------
__global__ void k_reduce_w(const float* __restrict__ hp) {
    int i = blockIdx.x * blockDim.x + threadIdx.x;
    if (i < NH * HID) {
        float s = 0.f;
#pragma unroll
        for (int d = 0; d < 16; d++) s += hp[i * 16 + d];
        g_W[i] = s;
    }
}

// ---------------- K2: LSH codes for keys AND queries in one launch -------------
// blocks 0..2047: keys (4 rows/warp); blocks 2048..2111: queries (4 rows/warp)
__global__ void k_hash_all(const float* __restrict__ keys, const float* __restrict__ query) {
    __shared__ float4 sW4[NH * 128];
    int tid = threadIdx.x;
    for (int i = tid; i < NH * 128; i += 256) sW4[i] = ((const float4*)g_W)[i];
    __syncthreads();
    int warp = tid >> 5, lane = tid & 31;
    const float* X;
    unsigned char* out;
    int r0;
    if (blockIdx.x < CAP / 32) {
        X = keys; out = g_kcode;
        r0 = (blockIdx.x * 8 + warp) * 4;
    } else {
        X = query; out = g_qcode;
        r0 = (((int)blockIdx.x - CAP / 32) * 8 + warp) * 4;
    }
    float acc[4][NH];
#pragma unroll
    for (int r = 0; r < 4; r++)
#pragma unroll
        for (int n = 0; n < NH; n++) acc[r][n] = 0.f;

#pragma unroll
    for (int i = 0; i < 4; i++) {
        int j = lane + 32 * i;
        float4 xv[4];
#pragma unroll
        for (int r = 0; r < 4; r++)
            xv[r] = ((const float4*)(X + (size_t)(r0 + r) * HID))[j];
#pragma unroll
        for (int n = 0; n < NH; n++) {
            float4 wv = sW4[n * 128 + j];
#pragma unroll
            for (int r = 0; r < 4; r++)
                acc[r][n] += xv[r].x * wv.x + xv[r].y * wv.y + xv[r].z * wv.z + xv[r].w * wv.w;
        }
    }
#pragma unroll
    for (int r = 0; r < 4; r++)
#pragma unroll
        for (int n = 0; n < NH; n++) {
#pragma unroll
            for (int off = 16; off > 0; off >>= 1)
                acc[r][n] += __shfl_xor_sync(0xffffffffu, acc[r][n], off);
        }
    if (lane == 0) {
#pragma unroll
        for (int r = 0; r < 4; r++) {
            unsigned c = 0;
#pragma unroll
            for (int n = 0; n < NH; n++)
                if (acc[r][n] > 0.f) c |= (1u << n);
            out[r0 + r] = (unsigned char)c;
        }
    }
}

// ---------------- K3: selection, MLP-aware ----------------
__device__ __forceinline__ int heavy_iter(int it, int b, unsigned pat, int total,
                                          int w, int lane, int tid, int* warpcnt) {
    uint4 v = ((const uint4*)g_kcode)[it * 512 + tid];
    unsigned e0 = __vcmpeq4(v.x, pat);
    unsigned e1 = __vcmpeq4(v.y, pat);
    unsigned e2 = __vcmpeq4(v.z, pat);
    unsigned e3 = __vcmpeq4(v.w, pat);
    int cnt = (__popc(e0) + __popc(e1) + __popc(e2) + __popc(e3)) >> 3;
    int wsum = cnt;
#pragma unroll
    for (int off = 16; off > 0; off >>= 1)
        wsum += __shfl_xor_sync(0xffffffffu, wsum, off);
    if (lane == 0) warpcnt[w] = wsum;
    __syncthreads();
    int blocksum = 0;
#pragma unroll
    for (int ww = 0; ww < 16; ww++) blocksum += warpcnt[ww];
    if (blocksum > 0 && total < TOPK) {
        int incl = cnt;
#pragma unroll
        for (int off = 1; off < 32; off <<= 1) {
            int t = __shfl_up_sync(0xffffffffu, incl, off);
            if (lane >= off) incl += t;
        }
        int excl = incl - cnt;
        int wbase = 0;
#pragma unroll
        for (int ww = 0; ww < 16; ww++)
            if (ww < w) wbase += warpcnt[ww];
        int r = total + wbase + excl;
        if (cnt > 0 && r < TOPK) {
            int idx0 = it * 8192 + tid * 16;
            unsigned e[4] = {e0, e1, e2, e3};
#pragma unroll
            for (int k = 0; k < 4; k++)
#pragma unroll
                for (int j = 0; j < 4; j++)
                    if ((e[k] >> (8 * j)) & 1u) {
                        if (r < TOPK) g_top[b * TOPK + r] = idx0 + k * 4 + j;
                        r++;
                    }
        }
    }
    __syncthreads();
    return blocksum;
}

__global__ void __launch_bounds__(512) k_select(void) {
    int b = blockIdx.x, tid = threadIdx.x;
    if (b < NCODE) {
        int w = tid >> 5, lane = tid & 31;
        __shared__ int warpcnt[16];
        __shared__ int wtot[16];
        unsigned pat = (unsigned)b * 0x01010101u;
        int total = 0;
        total += heavy_iter(0, b, pat, total, w, lane, tid, warpcnt);
        total += heavy_iter(1, b, pat, total, w, lane, tid, warpcnt);
        int mycnt = 0;
        if (total >= TOPK) {
#pragma unroll
            for (int it = 2; it < 8; it++) {
                uint4 v = ((const uint4*)g_kcode)[it * 512 + tid];
                mycnt += (__popc(__vcmpeq4(v.x, pat)) + __popc(__vcmpeq4(v.y, pat)) +
                          __popc(__vcmpeq4(v.z, pat)) + __popc(__vcmpeq4(v.w, pat))) >> 3;
            }
        } else {
#pragma unroll 1
            for (int it = 2; it < 8; it++)
                total += heavy_iter(it, b, pat, total, w, lane, tid, warpcnt);
        }
        int wsum = mycnt;
#pragma unroll
        for (int off = 16; off > 0; off >>= 1)
            wsum += __shfl_xor_sync(0xffffffffu, wsum, off);
        if (lane == 0) wtot[w] = wsum;
        __syncthreads();
        if (tid == 0) {
            int t = total;
#pragma unroll
            for (int ww = 0; ww < 16; ww++) t += wtot[ww];
            g_bcnt[b] = t;
        }
    } else {
        // ---- query grouping, one block of 512 ----
        __shared__ int qh[NCODE];
        __shared__ int qs2[NCODE];
        __shared__ int qoff[NCODE];
        if (tid < 256) qh[tid] = 0;
        __syncthreads();
        unsigned char my[BATCH / 512];
#pragma unroll
        for (int r = 0; r < BATCH / 512; r++) {
            my[r] = g_qcode[r * 512 + tid];
            atomicAdd(&qh[my[r]], 1);
        }
        __syncthreads();
        int v = 0;
        if (tid < 256) { v = qh[tid]; qs2[tid] = v; }
        __syncthreads();
        for (int off = 1; off < 256; off <<= 1) {
            int tmp = (tid < 256 && tid >= off) ? qs2[tid - off] : 0;
            __syncthreads();
            if (tid < 256) qs2[tid] += tmp;
            __syncthreads();
        }
        if (tid < 256) {
            int start = qs2[tid] - v;
            g_qbcnt[tid] = v;
            g_qbstart[tid] = start;
            qoff[tid] = start;
        }
        __syncthreads();
#pragma unroll
        for (int r = 0; r < BATCH / 512; r++) {
            int pos = atomicAdd(&qoff[my[r]], 1);
            g_qsorted[pos] = r * 512 + tid;
        }
    }
}

// ---------------- K4: grouped attention ----------------
__global__ void k_attn(const float* __restrict__ query,
                       const float* __restrict__ mkeys,
                       const float* __restrict__ mvals) {
    int code = blockIdx.x;
    int qcnt = g_qbcnt[code];
    if ((int)blockIdx.y * 8 >= qcnt) return;
    int tid = threadIdx.x;

    __shared__ int   sidx[TOPK];
    __shared__ float sq[8][HID];
    __shared__ float ssc[8][TOPK];
    __shared__ float swt[8][TOPK];
    __shared__ int   sqi[8];

    int kcnt = g_bcnt[code];
    if (kcnt >= TOPK) {
        if (tid < TOPK) sidx[tid] = g_top[code * TOPK + tid];
    } else if (tid < 32) {
        // exact (distance, index)-ordered fallback; astronomically rare
        int lane = tid;
        int got = 0;
        for (int d = 0; d <= NH && got < TOPK; d++) {
            for (int base = 0; base < CAP; base += 32) {
                int c = g_kcode[base + lane];
                bool hit = (__popc(c ^ code) == d);
                unsigned m = __ballot_sync(0xffffffffu, hit);
                int r = __popc(m & ((1u << lane) - 1u));
                if (hit && got + r < TOPK) sidx[got + r] = base + lane;
                got += __popc(m);
                if (got >= TOPK) break;
            }
        }
    }

    int qbase = g_qbstart[code];
    for (int g = blockIdx.y; g * 8 < qcnt; g += 4) {
        int qs = g * 8;
        int nq = qcnt - qs; if (nq > 8) nq = 8;
        if (tid < nq) sqi[tid] = g_qsorted[qbase + qs + tid];
        __syncthreads();
        for (int i = tid; i < nq * HID; i += 256) {
            int q = i >> 9, h = i & (HID - 1);
            sq[q][h] = query[(size_t)sqi[q] * HID + h];
        }
        __syncthreads();

        if (tid < 128) {
            int sub = tid & 7, kg = tid >> 3;
            const float4* kr0 = (const float4*)(mkeys + (size_t)sidx[kg] * HID);
            const float4* kr1 = (const float4*)(mkeys + (size_t)sidx[kg + 16] * HID);
            float a0[8], a1[8];
#pragma unroll
            for (int q = 0; q < 8; q++) { a0[q] = 0.f; a1[q] = 0.f; }
#pragma unroll
            for (int j = 0; j < 16; j++) {
                int jj = sub + 8 * j;
                float4 k0 = kr0[jj];
                float4 k1 = kr1[jj];
#pragma unroll
                for (int q = 0; q < 8; q++) {
                    float4 qv = ((const float4*)sq[q])[jj];
                    a0[q] += k0.x * qv.x + k0.y * qv.y + k0.z * qv.z + k0.w * qv.w;
                    a1[q] += k1.x * qv.x + k1.y * qv.y + k1.z * qv.z + k1.w * qv.w;
                }
            }
#pragma unroll
            for (int q = 0; q < 8; q++) {
#pragma unroll
                for (int off = 1; off < 8; off <<= 1) {
                    a0[q] += __shfl_xor_sync(0xffffffffu, a0[q], off);
                    a1[q] += __shfl_xor_sync(0xffffffffu, a1[q], off);
                }
            }
            if (sub == 0) {
#pragma unroll
                for (int q = 0; q < 8; q++) {
                    ssc[q][kg]      = a0[q] * 0.04419417382415922f;
                    ssc[q][kg + 16] = a1[q] * 0.04419417382415922f;
                }
            }
        }
        __syncthreads();

        {
            int q = tid >> 5, lane = tid & 31;
            float s = ssc[q][lane];
            float mx = s;
#pragma unroll
            for (int off = 16; off > 0; off >>= 1)
                mx = fmaxf(mx, __shfl_xor_sync(0xffffffffu, mx, off));
            float e = expf(s - mx);
            float sum = e;
#pragma unroll
            for (int off = 16; off > 0; off >>= 1)
                sum += __shfl_xor_sync(0xffffffffu, sum, off);
            swt[q][lane] = e / sum;
        }
        __syncthreads();

        float o0[8], o1[8];
#pragma unroll
        for (int q = 0; q < 8; q++) { o0[q] = 0.f; o1[q] = 0.f; }
#pragma unroll
        for (int k = 0; k < TOPK; k++) {   // fully unrolled: max loads in flight
            const float* vr = mvals + (size_t)sidx[k] * HID;
            float v0 = vr[tid];
            float v1 = vr[tid + 256];
#pragma unroll
            for (int q = 0; q < 8; q++) {
                float w = swt[q][k];
                o0[q] += w * v0;
                o1[q] += w * v1;
            }
        }
        for (int q = 0; q < nq; q++) {
            g_memout[(size_t)sqi[q] * HID + tid]       = o0[q];
            g_memout[(size_t)sqi[q] * HID + tid + 256] = o1[q];
        }
        __syncthreads();
    }
}

// ---------------- K5: fused single-pass 3xBF16 tensor-core GEMM ----------------
__device__ __forceinline__ void ldm_x4(uint32_t* r, uint32_t addr) {
    asm volatile("ldmatrix.sync.aligned.m8n8.x4.shared.b16 {%0,%1,%2,%3}, [%4];"
                 : "=r"(r[0]), "=r"(r[1]), "=r"(r[2]), "=r"(r[3]) : "r"(addr));
}
__device__ __forceinline__ void mma_bf16(float* d, const uint32_t* a, uint32_t b0, uint32_t b1) {
    asm volatile("mma.sync.aligned.m16n8k16.row.col.f32.bf16.bf16.f32 "
                 "{%0,%1,%2,%3},{%4,%5,%6,%7},{%8,%9},{%0,%1,%2,%3};"
                 : "+f"(d[0]), "+f"(d[1]), "+f"(d[2]), "+f"(d[3])
                 : "r"(a[0]), "r"(a[1]), "r"(a[2]), "r"(a[3]), "r"(b0), "r"(b1));
}
__device__ __forceinline__ void split2(float x, float y, uint32_t& hi, uint32_t& lo) {
    __nv_bfloat162 h = __float22bfloat162_rn(make_float2(x, y));
    float2 hf = __bfloat1622float2(h);
    __nv_bfloat162 l = __float22bfloat162_rn(make_float2(x - hf.x, y - hf.y));
    hi = *(uint32_t*)&h;
    lo = *(uint32_t*)&l;
}

__global__ void k_gemm_tc(const float* __restrict__ Wt,
                          const float* __restrict__ bias,
                          float* __restrict__ C) {
    const int LDS = 40;
    __shared__ __align__(16) __nv_bfloat16 sAhi[128 * LDS];
    __shared__ __align__(16) __nv_bfloat16 sAlo[128 * LDS];
    __shared__ __align__(16) __nv_bfloat16 sBhi[64 * LDS];
    __shared__ __align__(16) __nv_bfloat16 sBlo[64 * LDS];
    int tid = threadIdx.x;
    int w = tid >> 5, lane = tid & 31;
    int bm = blockIdx.y * 128, bn = blockIdx.x * 64;
    int wm = (w >> 1) * 32, wn = (w & 1) * 32;

    float acc[2][4][4];
#pragma unroll
    for (int mt = 0; mt < 2; mt++)
#pragma unroll
        for (int n8 = 0; n8 < 4; n8++)
#pragma unroll
            for (int i = 0; i < 4; i++) acc[mt][n8][i] = 0.f;

    uint32_t sAhi_u = (uint32_t)__cvta_generic_to_shared(sAhi);
    uint32_t sAlo_u = (uint32_t)__cvta_generic_to_shared(sAlo);
    uint32_t sBhi_u = (uint32_t)__cvta_generic_to_shared(sBhi);
    uint32_t sBlo_u = (uint32_t)__cvta_generic_to_shared(sBlo);
    int lrow = lane & 15, lch = lane >> 4;

    for (int k0 = 0; k0 < HID; k0 += 32) {
        __syncthreads();
#pragma unroll
        for (int t = 0; t < 4; t++) {
            int f = tid + t * 256;
            int row = f >> 3, c4 = f & 7;
            float4 v = *(const float4*)&g_memout[(size_t)(bm + row) * HID + k0 + c4 * 4];
            uint32_t h0, l0, h1, l1;
            split2(v.x, v.y, h0, l0);
            split2(v.z, v.w, h1, l1);
            *(uint2*)(sAhi + row * LDS + c4 * 4) = make_uint2(h0, h1);
            *(uint2*)(sAlo + row * LDS + c4 * 4) = make_uint2(l0, l1);
        }
#pragma unroll
        for (int t = 0; t < 2; t++) {
            int f = tid + t * 256;
            int row = f >> 3, c4 = f & 7;
            float4 v = *(const float4*)&Wt[(size_t)(bn + row) * HID + k0 + c4 * 4];
            uint32_t h0, l0, h1, l1;
            split2(v.x, v.y, h0, l0);
            split2(v.z, v.w, h1, l1);
            *(uint2*)(sBhi + row * LDS + c4 * 4) = make_uint2(h0, h1);
            *(uint2*)(sBlo + row * LDS + c4 * 4) = make_uint2(l0, l1);
        }
        __syncthreads();
#pragma unroll
        for (int ks = 0; ks < 2; ks++) {
            uint32_t ahi[2][4], alo[2][4], bhi[2][4], blo[2][4];
            int aoff = 2 * ((wm + lrow) * LDS + ks * 16 + lch * 8);
            int boff = 2 * ((wn + lrow) * LDS + ks * 16 + lch * 8);
#pragma unroll
            for (int mt = 0; mt < 2; mt++) {
                ldm_x4(ahi[mt], sAhi_u + aoff + 2 * mt * 16 * LDS);
                ldm_x4(alo[mt], sAlo_u + aoff + 2 * mt * 16 * LDS);
            }
#pragma unroll
            for (int nt = 0; nt < 2; nt++) {
                ldm_x4(bhi[nt], sBhi_u + boff + 2 * nt * 16 * LDS);
                ldm_x4(blo[nt], sBlo_u + boff + 2 * nt * 16 * LDS);
            }
#pragma unroll
            for (int mt = 0; mt < 2; mt++)
#pragma unroll
                for (int n8 = 0; n8 < 4; n8++) {
                    int nt = n8 >> 1, hh = n8 & 1;
                    mma_bf16(acc[mt][n8], ahi[mt], bhi[nt][hh], bhi[nt][hh + 2]);
                    mma_bf16(acc[mt][n8], alo[mt], bhi[nt][hh], bhi[nt][hh + 2]);
                    mma_bf16(acc[mt][n8], ahi[mt], blo[nt][hh], blo[nt][hh + 2]);
                }
        }
    }

    int r0 = bm + wm + (lane >> 2);
#pragma unroll
    for (int mt = 0; mt < 2; mt++) {
#pragma unroll
        for (int n8 = 0; n8 < 4; n8++) {
            int col = bn + wn + n8 * 8 + (lane & 3) * 2;
            float b0 = bias[col], b1 = bias[col + 1];
            int r = r0 + mt * 16;
            C[(size_t)r * HID + col]           = acc[mt][n8][0] + b0;
            C[(size_t)r * HID + col + 1]       = acc[mt][n8][1] + b1;
            C[(size_t)(r + 8) * HID + col]     = acc[mt][n8][2] + b0;
            C[(size_t)(r + 8) * HID + col + 1] = acc[mt][n8][3] + b1;
        }
    }
}

// ---------------- launch ----------------
extern "C" void kernel_launch(void* const* d_in, const int* in_sizes, int n_in,
                              void* d_out, int out_size) {
    const float* query = (const float*)d_in[0];
    const float* mkeys = (const float*)d_in[1];
    const float* mvals = (const float*)d_in[2];
    const float* hproj = (const float*)d_in[3];
    const float* outw  = (const float*)d_in[4];
    const float* outb  = (const float*)d_in[5];
    float* out = (float*)d_out;

    k_reduce_w<<<(NH * HID + 255) / 256, 256>>>(hproj);
    k_hash_all<<<CAP / 32 + BATCH / 32, 256>>>(mkeys, query);
    k_select<<<NCODE + 1, 512>>>();
    dim3 agrid(NCODE, 4);
    k_attn<<<agrid, 256>>>(query, mkeys, mvals);
    dim3 ggrid(HID / 64, BATCH / 128);
    k_gemm_tc<<<ggrid, 256>>>(outw, outb, out);
}

// round 13
// speedup vs baseline: 1.2534x; 1.0021x over previous
#include <cuda_runtime.h>
#include <cuda_bf16.h>
#include <cstdint>

#define CAP    65536
#define HID    512
#define NH     8
#define BATCH  2048
#define TOPK   32
#define NCODE  256

// ---------------- scratch (static device globals; no allocation) ----------------
__device__ float         g_W[NH * HID];
__device__ unsigned char g_qcode[BATCH];
__device__ unsigned char g_kcode[CAP];
__device__ int           g_top[NCODE * TOPK];   // ALWAYS-complete top-32 per code
__device__ int           g_bcnt[NCODE];
__device__ int           g_qbstart[NCODE];
__device__ int           g_qbcnt[NCODE];
__device__ int           g_qsorted[BATCH];
__device__ float         g_sc[BATCH * TOPK];    // raw scaled scores per query
__device__ float         g_memout[BATCH * HID];

// ---------------- K1: W[n][h] = sum_d hp[n][h][d] ----------------
__global__ void k_reduce_w(const float* __restrict__ hp) {
    int i = blockIdx.x * blockDim.x + threadIdx.x;
    if (i < NH * HID) {
        float s = 0.f;
#pragma unroll
        for (int d = 0; d < 16; d++) s += hp[i * 16 + d];
        g_W[i] = s;
    }
}

// ---------------- K2: LSH codes for keys AND queries in one launch -------------
__global__ void k_hash_all(const float* __restrict__ keys, const float* __restrict__ query) {
    __shared__ float4 sW4[NH * 128];
    int tid = threadIdx.x;
    for (int i = tid; i < NH * 128; i += 256) sW4[i] = ((const float4*)g_W)[i];
    __syncthreads();
    int warp = tid >> 5, lane = tid & 31;
    const float* X;
    unsigned char* out;
    int r0;
    if (blockIdx.x < CAP / 32) {
        X = keys; out = g_kcode;
        r0 = (blockIdx.x * 8 + warp) * 4;
    } else {
        X = query; out = g_qcode;
        r0 = (((int)blockIdx.x - CAP / 32) * 8 + warp) * 4;
    }
    float acc[4][NH];
#pragma unroll
    for (int r = 0; r < 4; r++)
#pragma unroll
        for (int n = 0; n < NH; n++) acc[r][n] = 0.f;

#pragma unroll
    for (int i = 0; i < 4; i++) {
        int j = lane + 32 * i;
        float4 xv[4];
#pragma unroll
        for (int r = 0; r < 4; r++)
            xv[r] = ((const float4*)(X + (size_t)(r0 + r) * HID))[j];
#pragma unroll
        for (int n = 0; n < NH; n++) {
            float4 wv = sW4[n * 128 + j];
#pragma unroll
            for (int r = 0; r < 4; r++)
                acc[r][n] += xv[r].x * wv.x + xv[r].y * wv.y + xv[r].z * wv.z + xv[r].w * wv.w;
        }
    }
#pragma unroll
    for (int r = 0; r < 4; r++)
#pragma unroll
        for (int n = 0; n < NH; n++) {
#pragma unroll
            for (int off = 16; off > 0; off >>= 1)
                acc[r][n] += __shfl_xor_sync(0xffffffffu, acc[r][n], off);
        }
    if (lane == 0) {
#pragma unroll
        for (int r = 0; r < 4; r++) {
            unsigned c = 0;
#pragma unroll
            for (int n = 0; n < NH; n++)
                if (acc[r][n] > 0.f) c |= (1u << n);
            out[r0 + r] = (unsigned char)c;
        }
    }
}

// ---------------- K3: selection (MLP-aware) + exact fallback fill ----------------
__device__ __forceinline__ int heavy_iter(int it, int b, unsigned pat, int total,
                                          int w, int lane, int tid, int* warpcnt) {
    uint4 v = ((const uint4*)g_kcode)[it * 512 + tid];
    unsigned e0 = __vcmpeq4(v.x, pat);
    unsigned e1 = __vcmpeq4(v.y, pat);
    unsigned e2 = __vcmpeq4(v.z, pat);
    unsigned e3 = __vcmpeq4(v.w, pat);
    int cnt = (__popc(e0) + __popc(e1) + __popc(e2) + __popc(e3)) >> 3;
    int wsum = cnt;
#pragma unroll
    for (int off = 16; off > 0; off >>= 1)
        wsum += __shfl_xor_sync(0xffffffffu, wsum, off);
    if (lane == 0) warpcnt[w] = wsum;
    __syncthreads();
    int blocksum = 0;
#pragma unroll
    for (int ww = 0; ww < 16; ww++) blocksum += warpcnt[ww];
    if (blocksum > 0 && total < TOPK) {
        int incl = cnt;
#pragma unroll
        for (int off = 1; off < 32; off <<= 1) {
            int t = __shfl_up_sync(0xffffffffu, incl, off);
            if (lane >= off) incl += t;
        }
        int excl = incl - cnt;
        int wbase = 0;
#pragma unroll
        for (int ww = 0; ww < 16; ww++)
            if (ww < w) wbase += warpcnt[ww];
        int r = total + wbase + excl;
        if (cnt > 0 && r < TOPK) {
            int idx0 = it * 8192 + tid * 16;
            unsigned e[4] = {e0, e1, e2, e3};
#pragma unroll
            for (int k = 0; k < 4; k++)
#pragma unroll
                for (int j = 0; j < 4; j++)
                    if ((e[k] >> (8 * j)) & 1u) {
                        if (r < TOPK) g_top[b * TOPK + r] = idx0 + k * 4 + j;
                        r++;
                    }
        }
    }
    __syncthreads();
    return blocksum;
}

__global__ void __launch_bounds__(512) k_select(void) {
    int b = blockIdx.x, tid = threadIdx.x;
    if (b < NCODE) {
        int w = tid >> 5, lane = tid & 31;
        __shared__ int warpcnt[16];
        __shared__ int wtot[16];
        unsigned pat = (unsigned)b * 0x01010101u;
        int total = 0;
        total += heavy_iter(0, b, pat, total, w, lane, tid, warpcnt);
        total += heavy_iter(1, b, pat, total, w, lane, tid, warpcnt);
        int mycnt = 0;
        if (total >= TOPK) {
#pragma unroll
            for (int it = 2; it < 8; it++) {
                uint4 v = ((const uint4*)g_kcode)[it * 512 + tid];
                mycnt += (__popc(__vcmpeq4(v.x, pat)) + __popc(__vcmpeq4(v.y, pat)) +
                          __popc(__vcmpeq4(v.z, pat)) + __popc(__vcmpeq4(v.w, pat))) >> 3;
            }
        } else {
#pragma unroll 1
            for (int it = 2; it < 8; it++)
                total += heavy_iter(it, b, pat, total, w, lane, tid, warpcnt);
        }
        // astronomically-rare exact fallback: fill g_top by (distance, index) order
        if (total < TOPK && tid == 0) {
            int got = 0;
            for (int d = 0; d <= NH && got < TOPK; d++)
                for (int i = 0; i < CAP && got < TOPK; i++)
                    if (__popc((int)g_kcode[i] ^ b) == d)
                        g_top[b * TOPK + got++] = i;
        }
        int wsum = mycnt;
#pragma unroll
        for (int off = 16; off > 0; off >>= 1)
            wsum += __shfl_xor_sync(0xffffffffu, wsum, off);
        if (lane == 0) wtot[w] = wsum;
        __syncthreads();
        if (tid == 0) {
            int t = total;
#pragma unroll
            for (int ww = 0; ww < 16; ww++) t += wtot[ww];
            g_bcnt[b] = t;
        }
    } else {
        // ---- query grouping, one block of 512 ----
        __shared__ int qh[NCODE];
        __shared__ int qs2[NCODE];
        __shared__ int qoff[NCODE];
        if (tid < 256) qh[tid] = 0;
        __syncthreads();
        unsigned char my[BATCH / 512];
#pragma unroll
        for (int r = 0; r < BATCH / 512; r++) {
            my[r] = g_qcode[r * 512 + tid];
            atomicAdd(&qh[my[r]], 1);
        }
        __syncthreads();
        int v = 0;
        if (tid < 256) { v = qh[tid]; qs2[tid] = v; }
        __syncthreads();
        for (int off = 1; off < 256; off <<= 1) {
            int tmp = (tid < 256 && tid >= off) ? qs2[tid - off] : 0;
            __syncthreads();
            if (tid < 256) qs2[tid] += tmp;
            __syncthreads();
        }
        if (tid < 256) {
            int start = qs2[tid] - v;
            g_qbcnt[tid] = v;
            g_qbstart[tid] = start;
            qoff[tid] = start;
        }
        __syncthreads();
#pragma unroll
        for (int r = 0; r < BATCH / 512; r++) {
            int pos = atomicAdd(&qoff[my[r]], 1);
            g_qsorted[pos] = r * 512 + tid;
        }
    }
}

// ---------------- K4a: scores. grid (code, keyhalf), 256 thr -------------------
__global__ void __launch_bounds__(256) k_attn_score(const float* __restrict__ query,
                                                    const float* __restrict__ mkeys) {
    int code = blockIdx.x, half = blockIdx.y;
    int qcnt = g_qbcnt[code];
    if (qcnt == 0) return;
    int tid = threadIdx.x;
    int kg = tid >> 4, sub = tid & 15;       // 16 keys x 16 partials
    int key = g_top[code * TOPK + half * 16 + kg];
    const float4* kr = (const float4*)(mkeys + (size_t)key * HID);

    __shared__ float sq[8][HID];
    __shared__ int   sqi[8];
    int qbase = g_qbstart[code];

    for (int g = 0; g * 8 < qcnt; g++) {
        int qs = g * 8;
        int nq = qcnt - qs; if (nq > 8) nq = 8;
        if (tid < nq) sqi[tid] = g_qsorted[qbase + qs + tid];
        __syncthreads();
        for (int i = tid; i < nq * HID; i += 256) {
            int q = i >> 9, h = i & (HID - 1);
            sq[q][h] = query[(size_t)sqi[q] * HID + h];
        }
        __syncthreads();

        float a[8];
#pragma unroll
        for (int q = 0; q < 8; q++) a[q] = 0.f;
#pragma unroll
        for (int j = 0; j < 8; j++) {
            int jj = sub + 16 * j;
            float4 kv = kr[jj];
#pragma unroll
            for (int q = 0; q < 8; q++) {
                float4 qv = ((const float4*)sq[q])[jj];
                a[q] += kv.x * qv.x + kv.y * qv.y + kv.z * qv.z + kv.w * qv.w;
            }
        }
#pragma unroll
        for (int q = 0; q < 8; q++) {
#pragma unroll
            for (int off = 1; off < 16; off <<= 1)
                a[q] += __shfl_xor_sync(0xffffffffu, a[q], off, 16);
        }
        if (sub == 0) {
            for (int q = 0; q < nq; q++)
                g_sc[(size_t)sqi[q] * TOPK + half * 16 + kg] = a[q] * 0.04419417382415922f;
        }
        __syncthreads();
    }
}

// ---------------- K4b: softmax + A*V. grid (code, 4 col-slices), 128 thr -------
__global__ void __launch_bounds__(128) k_attn_av(const float* __restrict__ mvals) {
    int code = blockIdx.x;
    int qcnt = g_qbcnt[code];
    if (qcnt == 0) return;
    int tid = threadIdx.x;
    int col = blockIdx.y * 128 + tid;

    __shared__ int   sidx[TOPK];
    __shared__ float ssc[8][TOPK];
    __shared__ float swt[8][TOPK];
    __shared__ int   sqi[8];
    if (tid < TOPK) sidx[tid] = g_top[code * TOPK + tid];
    int qbase = g_qbstart[code];

    for (int g = 0; g * 8 < qcnt; g++) {
        int qs = g * 8;
        int nq = qcnt - qs; if (nq > 8) nq = 8;
        if (tid < nq) sqi[tid] = g_qsorted[qbase + qs + tid];
        __syncthreads();
        for (int i = tid; i < nq * TOPK; i += 128) {
            int q = i >> 5, k = i & 31;
            ssc[q][k] = g_sc[(size_t)sqi[q] * TOPK + k];
        }
        __syncthreads();
        if (tid < nq) {   // serial softmax per query (32 elems, cheap)
            float mx = ssc[tid][0];
#pragma unroll
            for (int k = 1; k < TOPK; k++) mx = fmaxf(mx, ssc[tid][k]);
            float sum = 0.f;
            float e[TOPK];
#pragma unroll
            for (int k = 0; k < TOPK; k++) { e[k] = expf(ssc[tid][k] - mx); sum += e[k]; }
            float inv = 1.f / sum;
#pragma unroll
            for (int k = 0; k < TOPK; k++) swt[tid][k] = e[k] * inv;
        }
        __syncthreads();

        float o[8];
#pragma unroll
        for (int q = 0; q < 8; q++) o[q] = 0.f;
#pragma unroll
        for (int k = 0; k < TOPK; k++) {
            float v = mvals[(size_t)sidx[k] * HID + col];
#pragma unroll
            for (int q = 0; q < 8; q++) o[q] += swt[q][k] * v;
        }
        for (int q = 0; q < nq; q++)
            g_memout[(size_t)sqi[q] * HID + col] = o[q];
        __syncthreads();
    }
}

// ---------------- K5: fused single-pass 3xBF16 tensor-core GEMM ----------------
__device__ __forceinline__ void ldm_x4(uint32_t* r, uint32_t addr) {
    asm volatile("ldmatrix.sync.aligned.m8n8.x4.shared.b16 {%0,%1,%2,%3}, [%4];"
                 : "=r"(r[0]), "=r"(r[1]), "=r"(r[2]), "=r"(r[3]) : "r"(addr));
}
__device__ __forceinline__ void mma_bf16(float* d, const uint32_t* a, uint32_t b0, uint32_t b1) {
    asm volatile("mma.sync.aligned.m16n8k16.row.col.f32.bf16.bf16.f32 "
                 "{%0,%1,%2,%3},{%4,%5,%6,%7},{%8,%9},{%0,%1,%2,%3};"
                 : "+f"(d[0]), "+f"(d[1]), "+f"(d[2]), "+f"(d[3])
                 : "r"(a[0]), "r"(a[1]), "r"(a[2]), "r"(a[3]), "r"(b0), "r"(b1));
}
__device__ __forceinline__ void split2(float x, float y, uint32_t& hi, uint32_t& lo) {
    __nv_bfloat162 h = __float22bfloat162_rn(make_float2(x, y));
    float2 hf = __bfloat1622float2(h);
    __nv_bfloat162 l = __float22bfloat162_rn(make_float2(x - hf.x, y - hf.y));
    hi = *(uint32_t*)&h;
    lo = *(uint32_t*)&l;
}

__global__ void k_gemm_tc(const float* __restrict__ Wt,
                          const float* __restrict__ bias,
                          float* __restrict__ C) {
    const int LDS = 40;
    __shared__ __align__(16) __nv_bfloat16 sAhi[128 * LDS];
    __shared__ __align__(16) __nv_bfloat16 sAlo[128 * LDS];
    __shared__ __align__(16) __nv_bfloat16 sBhi[64 * LDS];
    __shared__ __align__(16) __nv_bfloat16 sBlo[64 * LDS];
    int tid = threadIdx.x;
    int w = tid >> 5, lane = tid & 31;
    int bm = blockIdx.y * 128, bn = blockIdx.x * 64;
    int wm = (w >> 1) * 32, wn = (w & 1) * 32;

    float acc[2][4][4];
#pragma unroll
    for (int mt = 0; mt < 2; mt++)
#pragma unroll
        for (int n8 = 0; n8 < 4; n8++)
#pragma unroll
            for (int i = 0; i < 4; i++) acc[mt][n8][i] = 0.f;

    uint32_t sAhi_u = (uint32_t)__cvta_generic_to_shared(sAhi);
    uint32_t sAlo_u = (uint32_t)__cvta_generic_to_shared(sAlo);
    uint32_t sBhi_u = (uint32_t)__cvta_generic_to_shared(sBhi);
    uint32_t sBlo_u = (uint32_t)__cvta_generic_to_shared(sBlo);
    int lrow = lane & 15, lch = lane >> 4;

    for (int k0 = 0; k0 < HID; k0 += 32) {
        __syncthreads();
#pragma unroll
        for (int t = 0; t < 4; t++) {
            int f = tid + t * 256;
            int row = f >> 3, c4 = f & 7;
            float4 v = *(const float4*)&g_memout[(size_t)(bm + row) * HID + k0 + c4 * 4];
            uint32_t h0, l0, h1, l1;
            split2(v.x, v.y, h0, l0);
            split2(v.z, v.w, h1, l1);
            *(uint2*)(sAhi + row * LDS + c4 * 4) = make_uint2(h0, h1);
            *(uint2*)(sAlo + row * LDS + c4 * 4) = make_uint2(l0, l1);
        }
#pragma unroll
        for (int t = 0; t < 2; t++) {
            int f = tid + t * 256;
            int row = f >> 3, c4 = f & 7;
            float4 v = *(const float4*)&Wt[(size_t)(bn + row) * HID + k0 + c4 * 4];
            uint32_t h0, l0, h1, l1;
            split2(v.x, v.y, h0, l0);
            split2(v.z, v.w, h1, l1);
            *(uint2*)(sBhi + row * LDS + c4 * 4) = make_uint2(h0, h1);
            *(uint2*)(sBlo + row * LDS + c4 * 4) = make_uint2(l0, l1);
        }
        __syncthreads();
#pragma unroll
        for (int ks = 0; ks < 2; ks++) {
            uint32_t ahi[2][4], alo[2][4], bhi[2][4], blo[2][4];
            int aoff = 2 * ((wm + lrow) * LDS + ks * 16 + lch * 8);
            int boff = 2 * ((wn + lrow) * LDS + ks * 16 + lch * 8);
#pragma unroll
            for (int mt = 0; mt < 2; mt++) {
                ldm_x4(ahi[mt], sAhi_u + aoff + 2 * mt * 16 * LDS);
                ldm_x4(alo[mt], sAlo_u + aoff + 2 * mt * 16 * LDS);
            }
#pragma unroll
            for (int nt = 0; nt < 2; nt++) {
                ldm_x4(bhi[nt], sBhi_u + boff + 2 * nt * 16 * LDS);
                ldm_x4(blo[nt], sBlo_u + boff + 2 * nt * 16 * LDS);
            }
#pragma unroll
            for (int mt = 0; mt < 2; mt++)
#pragma unroll
                for (int n8 = 0; n8 < 4; n8++) {
                    int nt = n8 >> 1, hh = n8 & 1;
                    mma_bf16(acc[mt][n8], ahi[mt], bhi[nt][hh], bhi[nt][hh + 2]);
                    mma_bf16(acc[mt][n8], alo[mt], bhi[nt][hh], bhi[nt][hh + 2]);
                    mma_bf16(acc[mt][n8], ahi[mt], blo[nt][hh], blo[nt][hh + 2]);
                }
        }
    }

    int r0 = bm + wm + (lane >> 2);
#pragma unroll
    for (int mt = 0; mt < 2; mt++) {
#pragma unroll
        for (int n8 = 0; n8 < 4; n8++) {
            int col = bn + wn + n8 * 8 + (lane & 3) * 2;
            float b0 = bias[col], b1 = bias[col + 1];
            int r = r0 + mt * 16;
            C[(size_t)r * HID + col]           = acc[mt][n8][0] + b0;
            C[(size_t)r * HID + col + 1]       = acc[mt][n8][1] + b1;
            C[(size_t)(r + 8) * HID + col]     = acc[mt][n8][2] + b0;
            C[(size_t)(r + 8) * HID + col + 1] = acc[mt][n8][3] + b1;
        }
    }
}

// ---------------- launch ----------------
extern "C" void kernel_launch(void* const* d_in, const int* in_sizes, int n_in,
                              void* d_out, int out_size) {
    const float* query = (const float*)d_in[0];
    const float* mkeys = (const float*)d_in[1];
    const float* mvals = (const float*)d_in[2];
    const float* hproj = (const float*)d_in[3];
    const float* outw  = (const float*)d_in[4];
    const float* outb  = (const float*)d_in[5];
    float* out = (float*)d_out;

    k_reduce_w<<<(NH * HID + 255) / 256, 256>>>(hproj);
    k_hash_all<<<CAP / 32 + BATCH / 32, 256>>>(mkeys, query);
    k_select<<<NCODE + 1, 512>>>();
    dim3 sgrid(NCODE, 2);
    k_attn_score<<<sgrid, 256>>>(query, mkeys);
    dim3 vgrid(NCODE, 4);
    k_attn_av<<<vgrid, 128>>>(mvals);
    dim3 ggrid(HID / 64, BATCH / 128);
    k_gemm_tc<<<ggrid, 256>>>(outw, outb, out);
}

// round 14
// speedup vs baseline: 1.2583x; 1.0040x over previous
#include <cuda_runtime.h>
#include <cuda_bf16.h>
#include <cstdint>

#define CAP    65536
#define HID    512
#define NH     8
#define BATCH  2048
#define TOPK   32
#define NCODE  256

// ---------------- scratch (static device globals; no allocation) ----------------
__device__ float         g_W[NH * HID];
__device__ unsigned char g_qcode[BATCH];
__device__ unsigned char g_kcode[CAP];
__device__ int           g_top[NCODE * TOPK];   // ALWAYS-complete top-32 per code
__device__ int           g_bcnt[NCODE];
__device__ int           g_qbstart[NCODE];
__device__ int           g_qbcnt[NCODE];
__device__ int           g_qsorted[BATCH];
__device__ float         g_sc[BATCH * TOPK];    // raw scaled scores per query
__device__ float         g_memout[BATCH * HID];

// ---------------- K1: W[n][h] = sum_d hp[n][h][d] ----------------
__global__ void k_reduce_w(const float* __restrict__ hp) {
    int i = blockIdx.x * blockDim.x + threadIdx.x;
    if (i < NH * HID) {
        float s = 0.f;
#pragma unroll
        for (int d = 0; d < 16; d++) s += hp[i * 16 + d];
        g_W[i] = s;
    }
}

// ---------------- K2: LSH codes for keys AND queries in one launch -------------
__global__ void k_hash_all(const float* __restrict__ keys, const float* __restrict__ query) {
    __shared__ float4 sW4[NH * 128];
    int tid = threadIdx.x;
    for (int i = tid; i < NH * 128; i += 256) sW4[i] = ((const float4*)g_W)[i];
    __syncthreads();
    int warp = tid >> 5, lane = tid & 31;
    const float* X;
    unsigned char* out;
    int r0;
    if (blockIdx.x < CAP / 32) {
        X = keys; out = g_kcode;
        r0 = (blockIdx.x * 8 + warp) * 4;
    } else {
        X = query; out = g_qcode;
        r0 = (((int)blockIdx.x - CAP / 32) * 8 + warp) * 4;
    }
    float acc[4][NH];
#pragma unroll
    for (int r = 0; r < 4; r++)
#pragma unroll
        for (int n = 0; n < NH; n++) acc[r][n] = 0.f;

#pragma unroll
    for (int i = 0; i < 4; i++) {
        int j = lane + 32 * i;
        float4 xv[4];
#pragma unroll
        for (int r = 0; r < 4; r++)
            xv[r] = ((const float4*)(X + (size_t)(r0 + r) * HID))[j];
#pragma unroll
        for (int n = 0; n < NH; n++) {
            float4 wv = sW4[n * 128 + j];
#pragma unroll
            for (int r = 0; r < 4; r++)
                acc[r][n] += xv[r].x * wv.x + xv[r].y * wv.y + xv[r].z * wv.z + xv[r].w * wv.w;
        }
    }
#pragma unroll
    for (int r = 0; r < 4; r++)
#pragma unroll
        for (int n = 0; n < NH; n++) {
#pragma unroll
            for (int off = 16; off > 0; off >>= 1)
                acc[r][n] += __shfl_xor_sync(0xffffffffu, acc[r][n], off);
        }
    if (lane == 0) {
#pragma unroll
        for (int r = 0; r < 4; r++) {
            unsigned c = 0;
#pragma unroll
            for (int n = 0; n < NH; n++)
                if (acc[r][n] > 0.f) c |= (1u << n);
            out[r0 + r] = (unsigned char)c;
        }
    }
}

// ---------------- K3: selection (MLP-aware) + exact fallback fill ----------------
__device__ __forceinline__ int heavy_iter(int it, int b, unsigned pat, int total,
                                          int w, int lane, int tid, int* warpcnt) {
    uint4 v = ((const uint4*)g_kcode)[it * 512 + tid];
    unsigned e0 = __vcmpeq4(v.x, pat);
    unsigned e1 = __vcmpeq4(v.y, pat);
    unsigned e2 = __vcmpeq4(v.z, pat);
    unsigned e3 = __vcmpeq4(v.w, pat);
    int cnt = (__popc(e0) + __popc(e1) + __popc(e2) + __popc(e3)) >> 3;
    int wsum = cnt;
#pragma unroll
    for (int off = 16; off > 0; off >>= 1)
        wsum += __shfl_xor_sync(0xffffffffu, wsum, off);
    if (lane == 0) warpcnt[w] = wsum;
    __syncthreads();
    int blocksum = 0;
#pragma unroll
    for (int ww = 0; ww < 16; ww++) blocksum += warpcnt[ww];
    if (blocksum > 0 && total < TOPK) {
        int incl = cnt;
#pragma unroll
        for (int off = 1; off < 32; off <<= 1) {
            int t = __shfl_up_sync(0xffffffffu, incl, off);
            if (lane >= off) incl += t;
        }
        int excl = incl - cnt;
        int wbase = 0;
#pragma unroll
        for (int ww = 0; ww < 16; ww++)
            if (ww < w) wbase += warpcnt[ww];
        int r = total + wbase + excl;
        if (cnt > 0 && r < TOPK) {
            int idx0 = it * 8192 + tid * 16;
            unsigned e[4] = {e0, e1, e2, e3};
#pragma unroll
            for (int k = 0; k < 4; k++)
#pragma unroll
                for (int j = 0; j < 4; j++)
                    if ((e[k] >> (8 * j)) & 1u) {
                        if (r < TOPK) g_top[b * TOPK + r] = idx0 + k * 4 + j;
                        r++;
                    }
        }
    }
    __syncthreads();
    return blocksum;
}

__global__ void __launch_bounds__(512) k_select(void) {
    int b = blockIdx.x, tid = threadIdx.x;
    if (b < NCODE) {
        int w = tid >> 5, lane = tid & 31;
        __shared__ int warpcnt[16];
        __shared__ int wtot[16];
        unsigned pat = (unsigned)b * 0x01010101u;
        int total = 0;
        total += heavy_iter(0, b, pat, total, w, lane, tid, warpcnt);
        total += heavy_iter(1, b, pat, total, w, lane, tid, warpcnt);
        int mycnt = 0;
        if (total >= TOPK) {
#pragma unroll
            for (int it = 2; it < 8; it++) {
                uint4 v = ((const uint4*)g_kcode)[it * 512 + tid];
                mycnt += (__popc(__vcmpeq4(v.x, pat)) + __popc(__vcmpeq4(v.y, pat)) +
                          __popc(__vcmpeq4(v.z, pat)) + __popc(__vcmpeq4(v.w, pat))) >> 3;
            }
        } else {
#pragma unroll 1
            for (int it = 2; it < 8; it++)
                total += heavy_iter(it, b, pat, total, w, lane, tid, warpcnt);
        }
        // astronomically-rare exact fallback: fill g_top by (distance, index) order
        if (total < TOPK && tid == 0) {
            int got = 0;
            for (int d = 0; d <= NH && got < TOPK; d++)
                for (int i = 0; i < CAP && got < TOPK; i++)
                    if (__popc((int)g_kcode[i] ^ b) == d)
                        g_top[b * TOPK + got++] = i;
        }
        int wsum = mycnt;
#pragma unroll
        for (int off = 16; off > 0; off >>= 1)
            wsum += __shfl_xor_sync(0xffffffffu, wsum, off);
        if (lane == 0) wtot[w] = wsum;
        __syncthreads();
        if (tid == 0) {
            int t = total;
#pragma unroll
            for (int ww = 0; ww < 16; ww++) t += wtot[ww];
            g_bcnt[b] = t;
        }
    } else {
        // ---- query grouping, one block of 512 ----
        __shared__ int qh[NCODE];
        __shared__ int qs2[NCODE];
        __shared__ int qoff[NCODE];
        if (tid < 256) qh[tid] = 0;
        __syncthreads();
        unsigned char my[BATCH / 512];
#pragma unroll
        for (int r = 0; r < BATCH / 512; r++) {
            my[r] = g_qcode[r * 512 + tid];
            atomicAdd(&qh[my[r]], 1);
        }
        __syncthreads();
        int v = 0;
        if (tid < 256) { v = qh[tid]; qs2[tid] = v; }
        __syncthreads();
        for (int off = 1; off < 256; off <<= 1) {
            int tmp = (tid < 256 && tid >= off) ? qs2[tid - off] : 0;
            __syncthreads();
            if (tid < 256) qs2[tid] += tmp;
            __syncthreads();
        }
        if (tid < 256) {
            int start = qs2[tid] - v;
            g_qbcnt[tid] = v;
            g_qbstart[tid] = start;
            qoff[tid] = start;
        }
        __syncthreads();
#pragma unroll
        for (int r = 0; r < BATCH / 512; r++) {
            int pos = atomicAdd(&qoff[my[r]], 1);
            g_qsorted[pos] = r * 512 + tid;
        }
    }
}

// ---------------- K4a: scores. grid (code, 4 parallel groups), 256 thr ---------
// 32 keys x 8 subsets per block; float4 query staging.
__global__ void __launch_bounds__(256) k_attn_score(const float* __restrict__ query,
                                                    const float* __restrict__ mkeys) {
    int code = blockIdx.x;
    int qcnt = g_qbcnt[code];
    if ((int)blockIdx.y * 8 >= qcnt) return;
    int tid = threadIdx.x;
    int kg = tid >> 3, sub = tid & 7;        // 32 keys x 8 partials
    int key = g_top[code * TOPK + kg];
    const float4* kr = (const float4*)(mkeys + (size_t)key * HID);

    __shared__ float sq[8][HID];
    __shared__ int   sqi[8];
    int qbase = g_qbstart[code];

    for (int g = blockIdx.y; g * 8 < qcnt; g += 4) {
        int qs = g * 8;
        int nq = qcnt - qs; if (nq > 8) nq = 8;
        if (tid < nq) sqi[tid] = g_qsorted[qbase + qs + tid];
        __syncthreads();
        // vectorized query staging: nq*128 float4, 256 threads
        for (int i = tid; i < nq * (HID / 4); i += 256) {
            int q = i >> 7, c4 = i & 127;
            ((float4*)sq[q])[c4] = ((const float4*)(query + (size_t)sqi[q] * HID))[c4];
        }
        __syncthreads();

        float a[8];
#pragma unroll
        for (int q = 0; q < 8; q++) a[q] = 0.f;
#pragma unroll
        for (int j = 0; j < 16; j++) {
            int jj = sub + 8 * j;
            float4 kv = kr[jj];
#pragma unroll
            for (int q = 0; q < 8; q++) {
                float4 qv = ((const float4*)sq[q])[jj];
                a[q] += kv.x * qv.x + kv.y * qv.y + kv.z * qv.z + kv.w * qv.w;
            }
        }
#pragma unroll
        for (int q = 0; q < 8; q++) {
#pragma unroll
            for (int off = 1; off < 8; off <<= 1)
                a[q] += __shfl_xor_sync(0xffffffffu, a[q], off, 8);
        }
        if (sub == 0) {
            for (int q = 0; q < nq; q++)
                g_sc[(size_t)sqi[q] * TOPK + kg] = a[q] * 0.04419417382415922f;
        }
        __syncthreads();
    }
}

// ---------------- K4b: softmax + A*V. grid (code, 4 slices, 2 groups), 128 thr -
__global__ void __launch_bounds__(128) k_attn_av(const float* __restrict__ mvals) {
    int code = blockIdx.x;
    int qcnt = g_qbcnt[code];
    if ((int)blockIdx.z * 8 >= qcnt) return;
    int tid = threadIdx.x;
    int col = blockIdx.y * 128 + tid;

    __shared__ int   sidx[TOPK];
    __shared__ float ssc[8][TOPK];
    __shared__ float swt[8][TOPK];
    __shared__ int   sqi[8];
    if (tid < TOPK) sidx[tid] = g_top[code * TOPK + tid];
    int qbase = g_qbstart[code];

    for (int g = blockIdx.z; g * 8 < qcnt; g += 2) {
        int qs = g * 8;
        int nq = qcnt - qs; if (nq > 8) nq = 8;
        if (tid < nq) sqi[tid] = g_qsorted[qbase + qs + tid];
        __syncthreads();
        for (int i = tid; i < nq * TOPK; i += 128) {
            int q = i >> 5, k = i & 31;
            ssc[q][k] = g_sc[(size_t)sqi[q] * TOPK + k];
        }
        __syncthreads();
        if (tid < nq) {   // serial softmax per query (32 elems, cheap)
            float mx = ssc[tid][0];
#pragma unroll
            for (int k = 1; k < TOPK; k++) mx = fmaxf(mx, ssc[tid][k]);
            float sum = 0.f;
            float e[TOPK];
#pragma unroll
            for (int k = 0; k < TOPK; k++) { e[k] = expf(ssc[tid][k] - mx); sum += e[k]; }
            float inv = 1.f / sum;
#pragma unroll
            for (int k = 0; k < TOPK; k++) swt[tid][k] = e[k] * inv;
        }
        __syncthreads();

        float o[8];
#pragma unroll
        for (int q = 0; q < 8; q++) o[q] = 0.f;
#pragma unroll
        for (int k = 0; k < TOPK; k++) {
            float v = mvals[(size_t)sidx[k] * HID + col];
#pragma unroll
            for (int q = 0; q < 8; q++) o[q] += swt[q][k] * v;
        }
        for (int q = 0; q < nq; q++)
            g_memout[(size_t)sqi[q] * HID + col] = o[q];
        __syncthreads();
    }
}

// ---------------- K5: fused single-pass 3xBF16 tensor-core GEMM ----------------
__device__ __forceinline__ void ldm_x4(uint32_t* r, uint32_t addr) {
    asm volatile("ldmatrix.sync.aligned.m8n8.x4.shared.b16 {%0,%1,%2,%3}, [%4];"
                 : "=r"(r[0]), "=r"(r[1]), "=r"(r[2]), "=r"(r[3]) : "r"(addr));
}
__device__ __forceinline__ void mma_bf16(float* d, const uint32_t* a, uint32_t b0, uint32_t b1) {
    asm volatile("mma.sync.aligned.m16n8k16.row.col.f32.bf16.bf16.f32 "
                 "{%0,%1,%2,%3},{%4,%5,%6,%7},{%8,%9},{%0,%1,%2,%3};"
                 : "+f"(d[0]), "+f"(d[1]), "+f"(d[2]), "+f"(d[3])
                 : "r"(a[0]), "r"(a[1]), "r"(a[2]), "r"(a[3]), "r"(b0), "r"(b1));
}
__device__ __forceinline__ void split2(float x, float y, uint32_t& hi, uint32_t& lo) {
    __nv_bfloat162 h = __float22bfloat162_rn(make_float2(x, y));
    float2 hf = __bfloat1622float2(h);
    __nv_bfloat162 l = __float22bfloat162_rn(make_float2(x - hf.x, y - hf.y));
    hi = *(uint32_t*)&h;
    lo = *(uint32_t*)&l;
}

__global__ void k_gemm_tc(const float* __restrict__ Wt,
                          const float* __restrict__ bias,
                          float* __restrict__ C) {
    const int LDS = 40;
    __shared__ __align__(16) __nv_bfloat16 sAhi[128 * LDS];
    __shared__ __align__(16) __nv_bfloat16 sAlo[128 * LDS];
    __shared__ __align__(16) __nv_bfloat16 sBhi[64 * LDS];
    __shared__ __align__(16) __nv_bfloat16 sBlo[64 * LDS];
    int tid = threadIdx.x;
    int w = tid >> 5, lane = tid & 31;
    int bm = blockIdx.y * 128, bn = blockIdx.x * 64;
    int wm = (w >> 1) * 32, wn = (w & 1) * 32;

    float acc[2][4][4];
#pragma unroll
    for (int mt = 0; mt < 2; mt++)
#pragma unroll
        for (int n8 = 0; n8 < 4; n8++)
#pragma unroll
            for (int i = 0; i < 4; i++) acc[mt][n8][i] = 0.f;

    uint32_t sAhi_u = (uint32_t)__cvta_generic_to_shared(sAhi);
    uint32_t sAlo_u = (uint32_t)__cvta_generic_to_shared(sAlo);
    uint32_t sBhi_u = (uint32_t)__cvta_generic_to_shared(sBhi);
    uint32_t sBlo_u = (uint32_t)__cvta_generic_to_shared(sBlo);
    int lrow = lane & 15, lch = lane >> 4;

    for (int k0 = 0; k0 < HID; k0 += 32) {
        __syncthreads();
#pragma unroll
        for (int t = 0; t < 4; t++) {
            int f = tid + t * 256;
            int row = f >> 3, c4 = f & 7;
            float4 v = *(const float4*)&g_memout[(size_t)(bm + row) * HID + k0 + c4 * 4];
            uint32_t h0, l0, h1, l1;
            split2(v.x, v.y, h0, l0);
            split2(v.z, v.w, h1, l1);
            *(uint2*)(sAhi + row * LDS + c4 * 4) = make_uint2(h0, h1);
            *(uint2*)(sAlo + row * LDS + c4 * 4) = make_uint2(l0, l1);
        }
#pragma unroll
        for (int t = 0; t < 2; t++) {
            int f = tid + t * 256;
            int row = f >> 3, c4 = f & 7;
            float4 v = *(const float4*)&Wt[(size_t)(bn + row) * HID + k0 + c4 * 4];
            uint32_t h0, l0, h1, l1;
            split2(v.x, v.y, h0, l0);
            split2(v.z, v.w, h1, l1);
            *(uint2*)(sBhi + row * LDS + c4 * 4) = make_uint2(h0, h1);
            *(uint2*)(sBlo + row * LDS + c4 * 4) = make_uint2(l0, l1);
        }
        __syncthreads();
#pragma unroll
        for (int ks = 0; ks < 2; ks++) {
            uint32_t ahi[2][4], alo[2][4], bhi[2][4], blo[2][4];
            int aoff = 2 * ((wm + lrow) * LDS + ks * 16 + lch * 8);
            int boff = 2 * ((wn + lrow) * LDS + ks * 16 + lch * 8);
#pragma unroll
            for (int mt = 0; mt < 2; mt++) {
                ldm_x4(ahi[mt], sAhi_u + aoff + 2 * mt * 16 * LDS);
                ldm_x4(alo[mt], sAlo_u + aoff + 2 * mt * 16 * LDS);
            }
#pragma unroll
            for (int nt = 0; nt < 2; nt++) {
                ldm_x4(bhi[nt], sBhi_u + boff + 2 * nt * 16 * LDS);
                ldm_x4(blo[nt], sBlo_u + boff + 2 * nt * 16 * LDS);
            }
#pragma unroll
            for (int mt = 0; mt < 2; mt++)
#pragma unroll
                for (int n8 = 0; n8 < 4; n8++) {
                    int nt = n8 >> 1, hh = n8 & 1;
                    mma_bf16(acc[mt][n8], ahi[mt], bhi[nt][hh], bhi[nt][hh + 2]);
                    mma_bf16(acc[mt][n8], alo[mt], bhi[nt][hh], bhi[nt][hh + 2]);
                    mma_bf16(acc[mt][n8], ahi[mt], blo[nt][hh], blo[nt][hh + 2]);
                }
        }
    }

    int r0 = bm + wm + (lane >> 2);
#pragma unroll
    for (int mt = 0; mt < 2; mt++) {
#pragma unroll
        for (int n8 = 0; n8 < 4; n8++) {
            int col = bn + wn + n8 * 8 + (lane & 3) * 2;
            float b0 = bias[col], b1 = bias[col + 1];
            int r = r0 + mt * 16;
            C[(size_t)r * HID + col]           = acc[mt][n8][0] + b0;
            C[(size_t)r * HID + col + 1]       = acc[mt][n8][1] + b1;
            C[(size_t)(r + 8) * HID + col]     = acc[mt][n8][2] + b0;
            C[(size_t)(r + 8) * HID + col + 1] = acc[mt][n8][3] + b1;
        }
    }
}

// ---------------- launch ----------------
extern "C" void kernel_launch(void* const* d_in, const int* in_sizes, int n_in,
                              void* d_out, int out_size) {
    const float* query = (const float*)d_in[0];
    const float* mkeys = (const float*)d_in[1];
    const float* mvals = (const float*)d_in[2];
    const float* hproj = (const float*)d_in[3];
    const float* outw  = (const float*)d_in[4];
    const float* outb  = (const float*)d_in[5];
    float* out = (float*)d_out;

    k_reduce_w<<<(NH * HID + 255) / 256, 256>>>(hproj);
    k_hash_all<<<CAP / 32 + BATCH / 32, 256>>>(mkeys, query);
    k_select<<<NCODE + 1, 512>>>();
    dim3 sgrid(NCODE, 4);
    k_attn_score<<<sgrid, 256>>>(query, mkeys);
    dim3 vgrid(NCODE, 4, 2);
    k_attn_av<<<vgrid, 128>>>(mvals);
    dim3 ggrid(HID / 64, BATCH / 128);
    k_gemm_tc<<<ggrid, 256>>>(outw, outb, out);
}